// round 1
// baseline (speedup 1.0000x reference)
#include <cuda_runtime.h>
#include <math.h>

// Problem constants
#define Bv      2
#define Tv      2048
#define Dv      1024
#define Hv      16
#define HDv     64
#define MAXLEN  2048
#define NBIAS   (2 * MAXLEN - 1)   // 4095
#define BT      (Bv * Tv)          // 4096

// ---------------------------------------------------------------------------
// Scratch (device globals; no allocation allowed in kernel_launch)
// ---------------------------------------------------------------------------
__device__ float g_qkv[BT * 3 * Dv];   // [B,T,3,H,HD]  48 MB
__device__ float g_attn[BT * Dv];      // [B,T,H*HD]    16 MB
__device__ float g_bias[NBIAS];        // projected RPE bias vector

// ---------------------------------------------------------------------------
// Kernel 1: bias_vec[j] = rel_pos[j,:] . rpe_w   (j in [0, 4095))
// ---------------------------------------------------------------------------
__global__ void rpe_bias_kernel(const float* __restrict__ rel_pos,
                                const float* __restrict__ rpe_w) {
    int j = blockIdx.x;
    int lane = threadIdx.x;                 // 32 threads
    float v = rel_pos[j * HDv + lane] * rpe_w[lane]
            + rel_pos[j * HDv + 32 + lane] * rpe_w[32 + lane];
    #pragma unroll
    for (int o = 16; o > 0; o >>= 1) v += __shfl_xor_sync(0xffffffffu, v, o);
    if (lane == 0) g_bias[j] = v;
}

// ---------------------------------------------------------------------------
// Kernel 2/4: C[M,N] = A[M,K] @ W[N,K]^T + bias[N]
// Tiles: BM=BN=128, BK=16; 256 threads; 8x8 per thread.
// ---------------------------------------------------------------------------
#define GBM 128
#define GBN 128
#define GBK 16

__global__ void __launch_bounds__(256)
sgemm_bias_kernel(const float* __restrict__ A, const float* __restrict__ W,
                  const float* __restrict__ bias, float* __restrict__ C,
                  int M, int N, int K) {
    __shared__ float As[GBK][GBM];
    __shared__ float Ws[GBK][GBN];

    const int tid = threadIdx.x;
    const int rowBase = (tid / 16) * 8;       // 0..120
    const int colBase = (tid % 16) * 8;       // 0..120
    const int bm = blockIdx.y * GBM;
    const int bn = blockIdx.x * GBN;

    const int lr = tid / 4;                   // 0..63
    const int lk = (tid % 4) * 4;             // 0,4,8,12

    float acc[8][8];
    #pragma unroll
    for (int i = 0; i < 8; ++i)
        #pragma unroll
        for (int j = 0; j < 8; ++j) acc[i][j] = 0.f;

    for (int k0 = 0; k0 < K; k0 += GBK) {
        #pragma unroll
        for (int h = 0; h < 2; ++h) {
            int r = h * 64 + lr;
            float4 a = *(const float4*)&A[(size_t)(bm + r) * K + k0 + lk];
            As[lk + 0][r] = a.x; As[lk + 1][r] = a.y;
            As[lk + 2][r] = a.z; As[lk + 3][r] = a.w;
            float4 w = *(const float4*)&W[(size_t)(bn + r) * K + k0 + lk];
            Ws[lk + 0][r] = w.x; Ws[lk + 1][r] = w.y;
            Ws[lk + 2][r] = w.z; Ws[lk + 3][r] = w.w;
        }
        __syncthreads();

        #pragma unroll
        for (int k = 0; k < GBK; ++k) {
            float a[8], b[8];
            *(float4*)&a[0] = *(const float4*)&As[k][rowBase];
            *(float4*)&a[4] = *(const float4*)&As[k][rowBase + 4];
            *(float4*)&b[0] = *(const float4*)&Ws[k][colBase];
            *(float4*)&b[4] = *(const float4*)&Ws[k][colBase + 4];
            #pragma unroll
            for (int i = 0; i < 8; ++i)
                #pragma unroll
                for (int j = 0; j < 8; ++j)
                    acc[i][j] = fmaf(a[i], b[j], acc[i][j]);
        }
        __syncthreads();
    }

    #pragma unroll
    for (int i = 0; i < 8; ++i) {
        int row = bm + rowBase + i;
        #pragma unroll
        for (int j = 0; j < 8; j += 4) {
            int col = bn + colBase + j;
            float4 o;
            o.x = acc[i][j + 0] + bias[col + 0];
            o.y = acc[i][j + 1] + bias[col + 1];
            o.z = acc[i][j + 2] + bias[col + 2];
            o.w = acc[i][j + 3] + bias[col + 3];
            *(float4*)&C[(size_t)row * N + col] = o;
        }
    }
}

// ---------------------------------------------------------------------------
// Kernel 3: flash attention with RPE bias.
// Block = (b, h, 64-row q tile). 256 threads; thread (ty,tx) owns a 4x4
// micro-tile: q rows ty*4.., k cols (then O d-cols) tx*4..
// smem (dynamic): Qs[d][q] 64x65, KPs 64x65 (K transposed, reused for P),
//                 Vs[k][d] 64x65, bias window 128.
// ---------------------------------------------------------------------------
#define FPAD 65
#define FSM_FLOATS (3 * 64 * FPAD + 128)
#define FSM_BYTES  (FSM_FLOATS * 4)

__global__ void __launch_bounds__(256)
flash_rpe_kernel() {
    extern __shared__ float sm[];
    float* Qs  = sm;                 // [64][65]  Qs[d*65 + q]
    float* KPs = Qs + 64 * FPAD;     // K: [d][k] ; later P: [k][q]
    float* Vs  = KPs + 64 * FPAD;    // [k][d]    Vs[k*65 + d]
    float* bs  = Vs + 64 * FPAD;     // [128] bias window

    const int b  = blockIdx.z;
    const int h  = blockIdx.y;
    const int qbase = blockIdx.x * 64;
    const int tid = threadIdx.x;
    const int ty = tid >> 4, tx = tid & 15;
    const int qr = ty * 4;           // q-row base
    const int kc = tx * 4;           // k-col / d-col base
    const float scale = 0.125f;      // HD^-0.5

    const int ldrow = tid >> 4;          // 0..15
    const int ldd4  = (tid & 15) * 4;    // 0..60

    // ---- load Q tile (transposed) ----
    #pragma unroll
    for (int it = 0; it < 4; ++it) {
        int r = it * 16 + ldrow;
        float4 v = *(const float4*)&g_qkv[(size_t)(b * Tv + qbase + r) * 3072
                                          + 0 * Dv + h * HDv + ldd4];
        Qs[(ldd4 + 0) * FPAD + r] = v.x;
        Qs[(ldd4 + 1) * FPAD + r] = v.y;
        Qs[(ldd4 + 2) * FPAD + r] = v.z;
        Qs[(ldd4 + 3) * FPAD + r] = v.w;
    }

    float m[4], l[4], o[4][4];
    #pragma unroll
    for (int i = 0; i < 4; ++i) {
        m[i] = -INFINITY; l[i] = 0.f;
        #pragma unroll
        for (int j = 0; j < 4; ++j) o[i][j] = 0.f;
    }

    for (int kt = 0; kt < Tv / 64; ++kt) {
        const int kbase = kt * 64;

        // ---- load K (transposed) and V tiles ----
        #pragma unroll
        for (int it = 0; it < 4; ++it) {
            int r = it * 16 + ldrow;
            size_t base = (size_t)(b * Tv + kbase + r) * 3072 + h * HDv + ldd4;
            float4 kv = *(const float4*)&g_qkv[base + 1 * Dv];
            KPs[(ldd4 + 0) * FPAD + r] = kv.x;
            KPs[(ldd4 + 1) * FPAD + r] = kv.y;
            KPs[(ldd4 + 2) * FPAD + r] = kv.z;
            KPs[(ldd4 + 3) * FPAD + r] = kv.w;
            float4 vv = *(const float4*)&g_qkv[base + 2 * Dv];
            Vs[r * FPAD + ldd4 + 0] = vv.x;
            Vs[r * FPAD + ldd4 + 1] = vv.y;
            Vs[r * FPAD + ldd4 + 2] = vv.z;
            Vs[r * FPAD + ldd4 + 3] = vv.w;
        }
        // bias window: index = (k - q) + 2047 ; local (kc+j)-(qr+i) in [-63,63]
        if (tid < 127) bs[tid] = g_bias[kbase - qbase - 63 + 2047 + tid];
        __syncthreads();

        // ---- S = Q K^T * scale + bias ----
        float s[4][4];
        #pragma unroll
        for (int i = 0; i < 4; ++i)
            #pragma unroll
            for (int j = 0; j < 4; ++j) s[i][j] = 0.f;

        #pragma unroll 8
        for (int d = 0; d < 64; ++d) {
            float a0 = Qs[d * FPAD + qr + 0];
            float a1 = Qs[d * FPAD + qr + 1];
            float a2 = Qs[d * FPAD + qr + 2];
            float a3 = Qs[d * FPAD + qr + 3];
            float b0 = KPs[d * FPAD + kc + 0];
            float b1 = KPs[d * FPAD + kc + 1];
            float b2 = KPs[d * FPAD + kc + 2];
            float b3 = KPs[d * FPAD + kc + 3];
            s[0][0] = fmaf(a0, b0, s[0][0]); s[0][1] = fmaf(a0, b1, s[0][1]);
            s[0][2] = fmaf(a0, b2, s[0][2]); s[0][3] = fmaf(a0, b3, s[0][3]);
            s[1][0] = fmaf(a1, b0, s[1][0]); s[1][1] = fmaf(a1, b1, s[1][1]);
            s[1][2] = fmaf(a1, b2, s[1][2]); s[1][3] = fmaf(a1, b3, s[1][3]);
            s[2][0] = fmaf(a2, b0, s[2][0]); s[2][1] = fmaf(a2, b1, s[2][1]);
            s[2][2] = fmaf(a2, b2, s[2][2]); s[2][3] = fmaf(a2, b3, s[2][3]);
            s[3][0] = fmaf(a3, b0, s[3][0]); s[3][1] = fmaf(a3, b1, s[3][1]);
            s[3][2] = fmaf(a3, b2, s[3][2]); s[3][3] = fmaf(a3, b3, s[3][3]);
        }
        #pragma unroll
        for (int i = 0; i < 4; ++i)
            #pragma unroll
            for (int j = 0; j < 4; ++j)
                s[i][j] = fmaf(s[i][j], scale, bs[(kc + j) - (qr + i) + 63]);

        __syncthreads();   // everyone done reading K before P overwrites it

        // ---- online softmax; write P into KPs as P[k][q] ----
        #pragma unroll
        for (int i = 0; i < 4; ++i) {
            float mx = fmaxf(fmaxf(s[i][0], s[i][1]), fmaxf(s[i][2], s[i][3]));
            #pragma unroll
            for (int off = 8; off > 0; off >>= 1)
                mx = fmaxf(mx, __shfl_xor_sync(0xffffffffu, mx, off));
            float mnew = fmaxf(m[i], mx);
            float corr = __expf(m[i] - mnew);
            float rs = 0.f;
            #pragma unroll
            for (int j = 0; j < 4; ++j) {
                float p = __expf(s[i][j] - mnew);
                KPs[(kc + j) * FPAD + qr + i] = p;
                rs += p;
            }
            #pragma unroll
            for (int off = 8; off > 0; off >>= 1)
                rs += __shfl_xor_sync(0xffffffffu, rs, off);
            l[i] = l[i] * corr + rs;
            m[i] = mnew;
            #pragma unroll
            for (int j = 0; j < 4; ++j) o[i][j] *= corr;
        }
        __syncthreads();   // P fully written before PV reads it

        // ---- O += P @ V ----
        #pragma unroll 8
        for (int kk = 0; kk < 64; ++kk) {
            float a0 = KPs[kk * FPAD + qr + 0];
            float a1 = KPs[kk * FPAD + qr + 1];
            float a2 = KPs[kk * FPAD + qr + 2];
            float a3 = KPs[kk * FPAD + qr + 3];
            float b0 = Vs[kk * FPAD + kc + 0];
            float b1 = Vs[kk * FPAD + kc + 1];
            float b2 = Vs[kk * FPAD + kc + 2];
            float b3 = Vs[kk * FPAD + kc + 3];
            o[0][0] = fmaf(a0, b0, o[0][0]); o[0][1] = fmaf(a0, b1, o[0][1]);
            o[0][2] = fmaf(a0, b2, o[0][2]); o[0][3] = fmaf(a0, b3, o[0][3]);
            o[1][0] = fmaf(a1, b0, o[1][0]); o[1][1] = fmaf(a1, b1, o[1][1]);
            o[1][2] = fmaf(a1, b2, o[1][2]); o[1][3] = fmaf(a1, b3, o[1][3]);
            o[2][0] = fmaf(a2, b0, o[2][0]); o[2][1] = fmaf(a2, b1, o[2][1]);
            o[2][2] = fmaf(a2, b2, o[2][2]); o[2][3] = fmaf(a2, b3, o[2][3]);
            o[3][0] = fmaf(a3, b0, o[3][0]); o[3][1] = fmaf(a3, b1, o[3][1]);
            o[3][2] = fmaf(a3, b2, o[3][2]); o[3][3] = fmaf(a3, b3, o[3][3]);
        }
        __syncthreads();   // done with P/V before next tile's loads
    }

    // ---- normalize and write [B,T,H*HD] ----
    #pragma unroll
    for (int i = 0; i < 4; ++i) {
        float inv = 1.f / l[i];
        int t = qbase + qr + i;
        #pragma unroll
        for (int j = 0; j < 4; ++j)
            g_attn[(size_t)(b * Tv + t) * Dv + h * HDv + kc + j] = o[i][j] * inv;
    }
}

// ---------------------------------------------------------------------------
// Launcher
// ---------------------------------------------------------------------------
extern "C" void kernel_launch(void* const* d_in, const int* in_sizes, int n_in,
                              void* d_out, int out_size) {
    const float* x       = (const float*)d_in[0];
    const float* qkv_w   = (const float*)d_in[1];
    const float* qkv_b   = (const float*)d_in[2];
    const float* out_w   = (const float*)d_in[3];
    const float* out_b   = (const float*)d_in[4];
    const float* rel_pos = (const float*)d_in[5];
    const float* rpe_w   = (const float*)d_in[6];
    float* out = (float*)d_out;

    float *qkv_p, *attn_p;
    cudaGetSymbolAddress((void**)&qkv_p,  g_qkv);
    cudaGetSymbolAddress((void**)&attn_p, g_attn);

    cudaFuncSetAttribute(flash_rpe_kernel,
                         cudaFuncAttributeMaxDynamicSharedMemorySize, FSM_BYTES);

    // 1) RPE bias projection
    rpe_bias_kernel<<<NBIAS, 32>>>(rel_pos, rpe_w);

    // 2) QKV projection: [4096,1024] @ [3072,1024]^T + b -> g_qkv
    {
        dim3 grid(3 * Dv / GBN, BT / GBM);
        sgemm_bias_kernel<<<grid, 256>>>(x, qkv_w, qkv_b, qkv_p,
                                         BT, 3 * Dv, Dv);
    }

    // 3) flash attention with RPE
    {
        dim3 grid(Tv / 64, Hv, Bv);
        flash_rpe_kernel<<<grid, 256, FSM_BYTES>>>();
    }

    // 4) output projection: [4096,1024] @ [1024,1024]^T + b -> d_out
    {
        dim3 grid(Dv / GBN, BT / GBM);
        sgemm_bias_kernel<<<grid, 256>>>(attn_p, out_w, out_b, out,
                                         BT, Dv, Dv);
    }
}

// round 3
// speedup vs baseline: 1.3946x; 1.3946x over previous
#include <cuda_runtime.h>
#include <math.h>
#include <stdint.h>

// Problem constants
#define Bv      2
#define Tv      2048
#define Dv      1024
#define Hv      16
#define HDv     64
#define MAXLEN  2048
#define NBIAS   (2 * MAXLEN - 1)   // 4095
#define BT      (Bv * Tv)          // 4096

// ---------------------------------------------------------------------------
// Scratch (device globals; no allocation allowed in kernel_launch)
// ---------------------------------------------------------------------------
__device__ float g_qkv[BT * 3 * Dv];   // [B,T,3,H,HD]  48 MB
__device__ float g_attn[BT * Dv];      // [B,T,H*HD]    16 MB
__device__ float g_bias[NBIAS];        // projected RPE bias vector

// ---------------------------------------------------------------------------
// PTX helpers (sm_103-base safe: cp.async + mma.sync only, NO tcgen05)
// ---------------------------------------------------------------------------
__device__ __forceinline__ uint32_t smem_u32(const void* p) {
    uint32_t a;
    asm("{ .reg .u64 t; cvta.to.shared.u64 t, %1; cvt.u32.u64 %0, t; }"
        : "=r"(a) : "l"(p));
    return a;
}
__device__ __forceinline__ void cp_async16(uint32_t saddr, const void* gptr) {
    asm volatile("cp.async.cg.shared.global [%0], [%1], 16;"
                 :: "r"(saddr), "l"(gptr) : "memory");
}
#define CP_COMMIT() asm volatile("cp.async.commit_group;" ::: "memory")
#define CP_WAIT(n)  asm volatile("cp.async.wait_group %0;" :: "n"(n) : "memory")

__device__ __forceinline__ uint32_t f2tf32(float f) {
    uint32_t u;
    asm("cvt.rna.tf32.f32 %0, %1;" : "=r"(u) : "f"(f));
    return u;
}
__device__ __forceinline__ void mma_tf32(float c[4], const uint32_t a[4],
                                         const uint32_t b[2]) {
    asm volatile(
        "mma.sync.aligned.m16n8k8.row.col.f32.tf32.tf32.f32 "
        "{%0,%1,%2,%3}, {%4,%5,%6,%7}, {%8,%9}, {%0,%1,%2,%3};"
        : "+f"(c[0]), "+f"(c[1]), "+f"(c[2]), "+f"(c[3])
        : "r"(a[0]), "r"(a[1]), "r"(a[2]), "r"(a[3]),
          "r"(b[0]), "r"(b[1]));
}

// ---------------------------------------------------------------------------
// Kernel 1: bias_vec[j] = rel_pos[j,:] . rpe_w
// ---------------------------------------------------------------------------
__global__ void rpe_bias_kernel(const float* __restrict__ rel_pos,
                                const float* __restrict__ rpe_w) {
    int j = blockIdx.x;
    int lane = threadIdx.x;
    float v = rel_pos[j * HDv + lane] * rpe_w[lane]
            + rel_pos[j * HDv + 32 + lane] * rpe_w[32 + lane];
    #pragma unroll
    for (int o = 16; o > 0; o >>= 1) v += __shfl_xor_sync(0xffffffffu, v, o);
    if (lane == 0) g_bias[j] = v;
}

// ---------------------------------------------------------------------------
// tf32 mma.sync GEMM:  C[M,N] = A[M,K] @ W[N,K]^T + bias[N]
// CTA tile 128x128, BK=32, 8 warps (2x4), warp tile 64x32.
// 2-stage cp.async pipeline. Smem row pitch 36 floats (conflict-free frags).
// ---------------------------------------------------------------------------
#define BK       32
#define APITCH   36                        // floats per smem row
#define TILE_F   (128 * APITCH)            // floats per operand tile
#define TILE_B   (TILE_F * 4)              // 18432 bytes
#define STG_B    (2 * TILE_B)              // 36864 bytes per stage
#define GSM_B    (2 * STG_B)               // 73728 bytes total

__global__ void __launch_bounds__(256)
tf32_gemm_bias(const float* __restrict__ A, const float* __restrict__ W,
               const float* __restrict__ bias, float* __restrict__ C,
               int M, int N, int K) {
    extern __shared__ float smf[];
    const uint32_t sbase = smem_u32(smf);
    const int tid  = threadIdx.x;
    const int wid  = tid >> 5;
    const int lane = tid & 31;
    const int q    = lane >> 2;        // 0..7
    const int t    = lane & 3;         // 0..3
    const int warp_m = wid >> 2;       // 0..1  (64 rows)
    const int warp_n = wid & 3;        // 0..3  (32 cols)
    const int bm = blockIdx.y * 128;
    const int bn = blockIdx.x * 128;
    const int nchunk = K / BK;         // 32

    float acc[4][4][4];
    #pragma unroll
    for (int mi = 0; mi < 4; ++mi)
        #pragma unroll
        for (int ni = 0; ni < 4; ++ni)
            #pragma unroll
            for (int e = 0; e < 4; ++e) acc[mi][ni][e] = 0.f;

    // ---- loader: chunk c -> stage s ----
    auto load_chunk = [&](int c, int s) {
        const uint32_t ab = sbase + s * STG_B;
        const uint32_t bb = ab + TILE_B;
        #pragma unroll
        for (int i = 0; i < 4; ++i) {
            int idx = tid + 256 * i;          // 0..1023
            int row = idx >> 3;
            int c16 = idx & 7;
            uint32_t doff = (uint32_t)(row * (APITCH * 4) + c16 * 16);
            const float* ga = A + (size_t)(bm + row) * K + c * BK + c16 * 4;
            const float* gw = W + (size_t)(bn + row) * K + c * BK + c16 * 4;
            cp_async16(ab + doff, ga);
            cp_async16(bb + doff, gw);
        }
    };

    // prologue
    load_chunk(0, 0); CP_COMMIT();
    load_chunk(1, 1); CP_COMMIT();

    for (int c = 0; c < nchunk; ++c) {
        const int s = c & 1;
        if (c + 1 < nchunk) { CP_WAIT(1); } else { CP_WAIT(0); }
        __syncthreads();

        const float* as = smf + s * (STG_B / 4);
        const float* bs = as + TILE_F;
        const int m_base = warp_m * 64;
        const int n_base = warp_n * 32;

        #pragma unroll
        for (int ks = 0; ks < 4; ++ks) {
            const int kc = ks * 8 + t;
            uint32_t af[4][4], bf[4][2];
            #pragma unroll
            for (int mi = 0; mi < 4; ++mi) {
                const float* p = as + (m_base + mi * 16 + q) * APITCH + kc;
                af[mi][0] = f2tf32(p[0]);
                af[mi][2] = f2tf32(p[4]);
                af[mi][1] = f2tf32(p[8 * APITCH]);
                af[mi][3] = f2tf32(p[8 * APITCH + 4]);
            }
            #pragma unroll
            for (int ni = 0; ni < 4; ++ni) {
                const float* p = bs + (n_base + ni * 8 + q) * APITCH + kc;
                bf[ni][0] = f2tf32(p[0]);
                bf[ni][1] = f2tf32(p[4]);
            }
            #pragma unroll
            for (int mi = 0; mi < 4; ++mi)
                #pragma unroll
                for (int ni = 0; ni < 4; ++ni)
                    mma_tf32(acc[mi][ni], af[mi], bf[ni]);
        }

        __syncthreads();
        if (c + 2 < nchunk) { load_chunk(c + 2, s); CP_COMMIT(); }
    }

    // ---- epilogue: c0,c1 -> (row, 2t..2t+1); c2,c3 -> (row+8, same cols) ----
    #pragma unroll
    for (int mi = 0; mi < 4; ++mi) {
        const int row0 = bm + warp_m * 64 + mi * 16 + q;
        #pragma unroll
        for (int ni = 0; ni < 4; ++ni) {
            const int col = bn + warp_n * 32 + ni * 8 + 2 * t;
            const float b0 = bias[col], b1 = bias[col + 1];
            float2 v0 = make_float2(acc[mi][ni][0] + b0, acc[mi][ni][1] + b1);
            float2 v1 = make_float2(acc[mi][ni][2] + b0, acc[mi][ni][3] + b1);
            *(float2*)&C[(size_t)row0 * N + col] = v0;
            *(float2*)&C[(size_t)(row0 + 8) * N + col] = v1;
        }
    }
}

// ---------------------------------------------------------------------------
// Kernel 3: flash attention with RPE bias (unchanged from passing R1 kernel).
// ---------------------------------------------------------------------------
#define FPAD 65
#define FSM_FLOATS (3 * 64 * FPAD + 128)
#define FSM_BYTES  (FSM_FLOATS * 4)

__global__ void __launch_bounds__(256)
flash_rpe_kernel() {
    extern __shared__ float sm[];
    float* Qs  = sm;
    float* KPs = Qs + 64 * FPAD;
    float* Vs  = KPs + 64 * FPAD;
    float* bs  = Vs + 64 * FPAD;

    const int b  = blockIdx.z;
    const int h  = blockIdx.y;
    const int qbase = blockIdx.x * 64;
    const int tid = threadIdx.x;
    const int ty = tid >> 4, tx = tid & 15;
    const int qr = ty * 4;
    const int kc = tx * 4;
    const float scale = 0.125f;

    const int ldrow = tid >> 4;
    const int ldd4  = (tid & 15) * 4;

    #pragma unroll
    for (int it = 0; it < 4; ++it) {
        int r = it * 16 + ldrow;
        float4 v = *(const float4*)&g_qkv[(size_t)(b * Tv + qbase + r) * 3072
                                          + 0 * Dv + h * HDv + ldd4];
        Qs[(ldd4 + 0) * FPAD + r] = v.x;
        Qs[(ldd4 + 1) * FPAD + r] = v.y;
        Qs[(ldd4 + 2) * FPAD + r] = v.z;
        Qs[(ldd4 + 3) * FPAD + r] = v.w;
    }

    float m[4], l[4], o[4][4];
    #pragma unroll
    for (int i = 0; i < 4; ++i) {
        m[i] = -INFINITY; l[i] = 0.f;
        #pragma unroll
        for (int j = 0; j < 4; ++j) o[i][j] = 0.f;
    }

    for (int kt = 0; kt < Tv / 64; ++kt) {
        const int kbase = kt * 64;

        #pragma unroll
        for (int it = 0; it < 4; ++it) {
            int r = it * 16 + ldrow;
            size_t base = (size_t)(b * Tv + kbase + r) * 3072 + h * HDv + ldd4;
            float4 kv = *(const float4*)&g_qkv[base + 1 * Dv];
            KPs[(ldd4 + 0) * FPAD + r] = kv.x;
            KPs[(ldd4 + 1) * FPAD + r] = kv.y;
            KPs[(ldd4 + 2) * FPAD + r] = kv.z;
            KPs[(ldd4 + 3) * FPAD + r] = kv.w;
            float4 vv = *(const float4*)&g_qkv[base + 2 * Dv];
            Vs[r * FPAD + ldd4 + 0] = vv.x;
            Vs[r * FPAD + ldd4 + 1] = vv.y;
            Vs[r * FPAD + ldd4 + 2] = vv.z;
            Vs[r * FPAD + ldd4 + 3] = vv.w;
        }
        if (tid < 127) bs[tid] = g_bias[kbase - qbase - 63 + 2047 + tid];
        __syncthreads();

        float s[4][4];
        #pragma unroll
        for (int i = 0; i < 4; ++i)
            #pragma unroll
            for (int j = 0; j < 4; ++j) s[i][j] = 0.f;

        #pragma unroll 8
        for (int d = 0; d < 64; ++d) {
            float a0 = Qs[d * FPAD + qr + 0];
            float a1 = Qs[d * FPAD + qr + 1];
            float a2 = Qs[d * FPAD + qr + 2];
            float a3 = Qs[d * FPAD + qr + 3];
            float b0 = KPs[d * FPAD + kc + 0];
            float b1 = KPs[d * FPAD + kc + 1];
            float b2 = KPs[d * FPAD + kc + 2];
            float b3 = KPs[d * FPAD + kc + 3];
            s[0][0] = fmaf(a0, b0, s[0][0]); s[0][1] = fmaf(a0, b1, s[0][1]);
            s[0][2] = fmaf(a0, b2, s[0][2]); s[0][3] = fmaf(a0, b3, s[0][3]);
            s[1][0] = fmaf(a1, b0, s[1][0]); s[1][1] = fmaf(a1, b1, s[1][1]);
            s[1][2] = fmaf(a1, b2, s[1][2]); s[1][3] = fmaf(a1, b3, s[1][3]);
            s[2][0] = fmaf(a2, b0, s[2][0]); s[2][1] = fmaf(a2, b1, s[2][1]);
            s[2][2] = fmaf(a2, b2, s[2][2]); s[2][3] = fmaf(a2, b3, s[2][3]);
            s[3][0] = fmaf(a3, b0, s[3][0]); s[3][1] = fmaf(a3, b1, s[3][1]);
            s[3][2] = fmaf(a3, b2, s[3][2]); s[3][3] = fmaf(a3, b3, s[3][3]);
        }
        #pragma unroll
        for (int i = 0; i < 4; ++i)
            #pragma unroll
            for (int j = 0; j < 4; ++j)
                s[i][j] = fmaf(s[i][j], scale, bs[(kc + j) - (qr + i) + 63]);

        __syncthreads();

        #pragma unroll
        for (int i = 0; i < 4; ++i) {
            float mx = fmaxf(fmaxf(s[i][0], s[i][1]), fmaxf(s[i][2], s[i][3]));
            #pragma unroll
            for (int off = 8; off > 0; off >>= 1)
                mx = fmaxf(mx, __shfl_xor_sync(0xffffffffu, mx, off));
            float mnew = fmaxf(m[i], mx);
            float corr = __expf(m[i] - mnew);
            float rs = 0.f;
            #pragma unroll
            for (int j = 0; j < 4; ++j) {
                float p = __expf(s[i][j] - mnew);
                KPs[(kc + j) * FPAD + qr + i] = p;
                rs += p;
            }
            #pragma unroll
            for (int off = 8; off > 0; off >>= 1)
                rs += __shfl_xor_sync(0xffffffffu, rs, off);
            l[i] = l[i] * corr + rs;
            m[i] = mnew;
            #pragma unroll
            for (int j = 0; j < 4; ++j) o[i][j] *= corr;
        }
        __syncthreads();

        #pragma unroll 8
        for (int kk = 0; kk < 64; ++kk) {
            float a0 = KPs[kk * FPAD + qr + 0];
            float a1 = KPs[kk * FPAD + qr + 1];
            float a2 = KPs[kk * FPAD + qr + 2];
            float a3 = KPs[kk * FPAD + qr + 3];
            float b0 = Vs[kk * FPAD + kc + 0];
            float b1 = Vs[kk * FPAD + kc + 1];
            float b2 = Vs[kk * FPAD + kc + 2];
            float b3 = Vs[kk * FPAD + kc + 3];
            o[0][0] = fmaf(a0, b0, o[0][0]); o[0][1] = fmaf(a0, b1, o[0][1]);
            o[0][2] = fmaf(a0, b2, o[0][2]); o[0][3] = fmaf(a0, b3, o[0][3]);
            o[1][0] = fmaf(a1, b0, o[1][0]); o[1][1] = fmaf(a1, b1, o[1][1]);
            o[1][2] = fmaf(a1, b2, o[1][2]); o[1][3] = fmaf(a1, b3, o[1][3]);
            o[2][0] = fmaf(a2, b0, o[2][0]); o[2][1] = fmaf(a2, b1, o[2][1]);
            o[2][2] = fmaf(a2, b2, o[2][2]); o[2][3] = fmaf(a2, b3, o[2][3]);
            o[3][0] = fmaf(a3, b0, o[3][0]); o[3][1] = fmaf(a3, b1, o[3][1]);
            o[3][2] = fmaf(a3, b2, o[3][2]); o[3][3] = fmaf(a3, b3, o[3][3]);
        }
        __syncthreads();
    }

    #pragma unroll
    for (int i = 0; i < 4; ++i) {
        float inv = 1.f / l[i];
        int t = qbase + qr + i;
        #pragma unroll
        for (int j = 0; j < 4; ++j)
            g_attn[(size_t)(b * Tv + t) * Dv + h * HDv + kc + j] = o[i][j] * inv;
    }
}

// ---------------------------------------------------------------------------
// Launcher
// ---------------------------------------------------------------------------
extern "C" void kernel_launch(void* const* d_in, const int* in_sizes, int n_in,
                              void* d_out, int out_size) {
    const float* x       = (const float*)d_in[0];
    const float* qkv_w   = (const float*)d_in[1];
    const float* qkv_b   = (const float*)d_in[2];
    const float* out_w   = (const float*)d_in[3];
    const float* out_b   = (const float*)d_in[4];
    const float* rel_pos = (const float*)d_in[5];
    const float* rpe_w   = (const float*)d_in[6];
    float* out = (float*)d_out;

    float *qkv_p, *attn_p;
    cudaGetSymbolAddress((void**)&qkv_p,  g_qkv);
    cudaGetSymbolAddress((void**)&attn_p, g_attn);

    cudaFuncSetAttribute(flash_rpe_kernel,
                         cudaFuncAttributeMaxDynamicSharedMemorySize, FSM_BYTES);
    cudaFuncSetAttribute(tf32_gemm_bias,
                         cudaFuncAttributeMaxDynamicSharedMemorySize, GSM_B);

    // 1) RPE bias projection
    rpe_bias_kernel<<<NBIAS, 32>>>(rel_pos, rpe_w);

    // 2) QKV projection: [4096,1024] @ [3072,1024]^T + b -> g_qkv (tf32 mma.sync)
    {
        dim3 grid(3 * Dv / 128, BT / 128);
        tf32_gemm_bias<<<grid, 256, GSM_B>>>(x, qkv_w, qkv_b, qkv_p,
                                             BT, 3 * Dv, Dv);
    }

    // 3) flash attention with RPE
    {
        dim3 grid(Tv / 64, Hv, Bv);
        flash_rpe_kernel<<<grid, 256, FSM_BYTES>>>();
    }

    // 4) output projection: [4096,1024] @ [1024,1024]^T + b -> d_out (tf32)
    {
        dim3 grid(Dv / 128, BT / 128);
        tf32_gemm_bias<<<grid, 256, GSM_B>>>(attn_p, out_w, out_b, out,
                                             BT, Dv, Dv);
    }
}

// round 4
// speedup vs baseline: 3.0476x; 2.1852x over previous
#include <cuda_runtime.h>
#include <math.h>
#include <stdint.h>

// Problem constants
#define Bv      2
#define Tv      2048
#define Dv      1024
#define Hv      16
#define HDv     64
#define MAXLEN  2048
#define NBIAS   (2 * MAXLEN - 1)   // 4095
#define BT      (Bv * Tv)          // 4096

// ---------------------------------------------------------------------------
// Scratch (device globals)
// ---------------------------------------------------------------------------
__device__ float g_qkv[BT * 3 * Dv];   // [B,T,3,H,HD]  48 MB
__device__ float g_attn[BT * Dv];      // [B,T,H*HD]    16 MB
__device__ float g_bias[4096];         // projected RPE bias (padded from 4095)

// ---------------------------------------------------------------------------
// PTX helpers (sm_103-base safe: cp.async + mma.sync only)
// ---------------------------------------------------------------------------
__device__ __forceinline__ uint32_t smem_u32(const void* p) {
    uint32_t a;
    asm("{ .reg .u64 t; cvta.to.shared.u64 t, %1; cvt.u32.u64 %0, t; }"
        : "=r"(a) : "l"(p));
    return a;
}
__device__ __forceinline__ void cp_async16(uint32_t saddr, const void* gptr) {
    asm volatile("cp.async.cg.shared.global [%0], [%1], 16;"
                 :: "r"(saddr), "l"(gptr) : "memory");
}
#define CP_COMMIT() asm volatile("cp.async.commit_group;" ::: "memory")
#define CP_WAIT(n)  asm volatile("cp.async.wait_group %0;" :: "n"(n) : "memory")

__device__ __forceinline__ uint32_t f2tf32(float f) {
    uint32_t u;
    asm("cvt.rna.tf32.f32 %0, %1;" : "=r"(u) : "f"(f));
    return u;
}
__device__ __forceinline__ void mma_tf32(float c[4], const uint32_t a[4],
                                         const uint32_t b[2]) {
    asm volatile(
        "mma.sync.aligned.m16n8k8.row.col.f32.tf32.tf32.f32 "
        "{%0,%1,%2,%3}, {%4,%5,%6,%7}, {%8,%9}, {%0,%1,%2,%3};"
        : "+f"(c[0]), "+f"(c[1]), "+f"(c[2]), "+f"(c[3])
        : "r"(a[0]), "r"(a[1]), "r"(a[2]), "r"(a[3]),
          "r"(b[0]), "r"(b[1]));
}

// ---------------------------------------------------------------------------
// Kernel 1: bias_vec[j] = rel_pos[j,:] . rpe_w
// ---------------------------------------------------------------------------
__global__ void rpe_bias_kernel(const float* __restrict__ rel_pos,
                                const float* __restrict__ rpe_w) {
    int j = blockIdx.x;
    int lane = threadIdx.x;
    float v = rel_pos[j * HDv + lane] * rpe_w[lane]
            + rel_pos[j * HDv + 32 + lane] * rpe_w[32 + lane];
    #pragma unroll
    for (int o = 16; o > 0; o >>= 1) v += __shfl_xor_sync(0xffffffffu, v, o);
    if (lane == 0) g_bias[j] = v;
}

// ---------------------------------------------------------------------------
// tf32 mma.sync GEMM (unchanged from passing R3 kernel)
// ---------------------------------------------------------------------------
#define BK       32
#define APITCH   36
#define TILE_F   (128 * APITCH)
#define TILE_B   (TILE_F * 4)
#define STG_B    (2 * TILE_B)
#define GSM_B    (2 * STG_B)

__global__ void __launch_bounds__(256)
tf32_gemm_bias(const float* __restrict__ A, const float* __restrict__ W,
               const float* __restrict__ bias, float* __restrict__ C,
               int M, int N, int K) {
    extern __shared__ float smf[];
    const uint32_t sbase = smem_u32(smf);
    const int tid  = threadIdx.x;
    const int wid  = tid >> 5;
    const int lane = tid & 31;
    const int q    = lane >> 2;
    const int t    = lane & 3;
    const int warp_m = wid >> 2;
    const int warp_n = wid & 3;
    const int bm = blockIdx.y * 128;
    const int bn = blockIdx.x * 128;
    const int nchunk = K / BK;

    float acc[4][4][4];
    #pragma unroll
    for (int mi = 0; mi < 4; ++mi)
        #pragma unroll
        for (int ni = 0; ni < 4; ++ni)
            #pragma unroll
            for (int e = 0; e < 4; ++e) acc[mi][ni][e] = 0.f;

    auto load_chunk = [&](int c, int s) {
        const uint32_t ab = sbase + s * STG_B;
        const uint32_t bb = ab + TILE_B;
        #pragma unroll
        for (int i = 0; i < 4; ++i) {
            int idx = tid + 256 * i;
            int row = idx >> 3;
            int c16 = idx & 7;
            uint32_t doff = (uint32_t)(row * (APITCH * 4) + c16 * 16);
            cp_async16(ab + doff, A + (size_t)(bm + row) * K + c * BK + c16 * 4);
            cp_async16(bb + doff, W + (size_t)(bn + row) * K + c * BK + c16 * 4);
        }
    };

    load_chunk(0, 0); CP_COMMIT();
    load_chunk(1, 1); CP_COMMIT();

    for (int c = 0; c < nchunk; ++c) {
        const int s = c & 1;
        if (c + 1 < nchunk) { CP_WAIT(1); } else { CP_WAIT(0); }
        __syncthreads();

        const float* as = smf + s * (STG_B / 4);
        const float* bs = as + TILE_F;
        const int m_base = warp_m * 64;
        const int n_base = warp_n * 32;

        #pragma unroll
        for (int ks = 0; ks < 4; ++ks) {
            const int kc = ks * 8 + t;
            uint32_t af[4][4], bf[4][2];
            #pragma unroll
            for (int mi = 0; mi < 4; ++mi) {
                const float* p = as + (m_base + mi * 16 + q) * APITCH + kc;
                af[mi][0] = f2tf32(p[0]);
                af[mi][2] = f2tf32(p[4]);
                af[mi][1] = f2tf32(p[8 * APITCH]);
                af[mi][3] = f2tf32(p[8 * APITCH + 4]);
            }
            #pragma unroll
            for (int ni = 0; ni < 4; ++ni) {
                const float* p = bs + (n_base + ni * 8 + q) * APITCH + kc;
                bf[ni][0] = f2tf32(p[0]);
                bf[ni][1] = f2tf32(p[4]);
            }
            #pragma unroll
            for (int mi = 0; mi < 4; ++mi)
                #pragma unroll
                for (int ni = 0; ni < 4; ++ni)
                    mma_tf32(acc[mi][ni], af[mi], bf[ni]);
        }

        __syncthreads();
        if (c + 2 < nchunk) { load_chunk(c + 2, s); CP_COMMIT(); }
    }

    #pragma unroll
    for (int mi = 0; mi < 4; ++mi) {
        const int row0 = bm + warp_m * 64 + mi * 16 + q;
        #pragma unroll
        for (int ni = 0; ni < 4; ++ni) {
            const int col = bn + warp_n * 32 + ni * 8 + 2 * t;
            const float b0 = bias[col], b1 = bias[col + 1];
            float2 v0 = make_float2(acc[mi][ni][0] + b0, acc[mi][ni][1] + b1);
            float2 v1 = make_float2(acc[mi][ni][2] + b0, acc[mi][ni][3] + b1);
            *(float2*)&C[(size_t)row0 * N + col] = v0;
            *(float2*)&C[(size_t)(row0 + 8) * N + col] = v1;
        }
    }
}

// ---------------------------------------------------------------------------
// Kernel 3: flash attention with RPE, tf32 mma.sync version.
// CTA: 128 q-rows x one (b,h); 8 warps, warp w owns rows [16w,16w+16).
// KT=64 keys/iter, 32 iters, double-buffered cp.async K/V/bias.
// Pitches: Q/K/P = 68 floats (conflict-free 4q+t), V = 72 (conflict-free 8t+q).
// ---------------------------------------------------------------------------
#define QT   128
#define KT   64
#define PA   68
#define PVt  72
#define OFF_Q   0
#define OFF_P   (OFF_Q + QT * PA)               // 8704
#define OFF_K   (OFF_P + QT * PA)               // 17408
#define OFF_V   (OFF_K + 2 * KT * PA)           // 26112
#define OFF_BW  (OFF_V + 2 * KT * PVt)          // 35328
#define FSM2_FLOATS (OFF_BW + 2 * 192)          // 35712
#define FSM2_BYTES  (FSM2_FLOATS * 4)           // 142848

__global__ void __launch_bounds__(256)
flash_rpe_mma() {
    extern __shared__ float sm[];
    const uint32_t sb = smem_u32(sm);
    const int b = blockIdx.z, h = blockIdx.y;
    const int qbase = blockIdx.x * QT;
    const int tid = threadIdx.x, wid = tid >> 5, lane = tid & 31;
    const int q = lane >> 2, t = lane & 3;
    const int mb = wid * 16;
    const float scale = 0.125f;

    // ---- load Q tile (plain stores) ----
    #pragma unroll
    for (int i = 0; i < 8; ++i) {
        int idx = tid + 256 * i;        // 0..2047
        int row = idx >> 4;             // 0..127
        int c4  = (idx & 15) * 4;
        float4 v = *(const float4*)&g_qkv[(size_t)(b * Tv + qbase + row) * 3072
                                          + h * HDv + c4];
        float* p = sm + OFF_Q + row * PA + c4;
        p[0] = v.x; p[1] = v.y; p[2] = v.z; p[3] = v.w;
    }

    // ---- K/V/bias loader: chunk kt -> stage s ----
    auto load_kv = [&](int kt, int s) {
        const int kbase = kt * KT;
        const uint32_t kb = sb + (OFF_K + s * KT * PA) * 4;
        const uint32_t vb = sb + (OFF_V + s * KT * PVt) * 4;
        #pragma unroll
        for (int i = 0; i < 4; ++i) {
            int idx = tid + 256 * i;    // 0..1023
            int row = idx >> 4;         // 0..63
            int c16 = idx & 15;
            size_t gb = (size_t)(b * Tv + kbase + row) * 3072 + h * HDv + c16 * 4;
            cp_async16(kb + row * (PA * 4)  + c16 * 16, &g_qkv[gb + 1024]);
            cp_async16(vb + row * (PVt * 4) + c16 * 16, &g_qkv[gb + 2048]);
        }
        if (tid < 48) {
            int base = kbase - qbase + 1920;   // multiple of 4 floats (16B)
            cp_async16(sb + (OFF_BW + s * 192 + tid * 4) * 4,
                       &g_bias[base + tid * 4]);
        }
    };

    load_kv(0, 0); CP_COMMIT();
    load_kv(1, 1); CP_COMMIT();

    float m0 = -INFINITY, m1 = -INFINITY, l0 = 0.f, l1 = 0.f;
    float ao[8][4];
    #pragma unroll
    for (int ni = 0; ni < 8; ++ni)
        #pragma unroll
        for (int e = 0; e < 4; ++e) ao[ni][e] = 0.f;

    for (int kt = 0; kt < Tv / KT; ++kt) {
        const int s = kt & 1;
        if (kt < Tv / KT - 1) { CP_WAIT(1); } else { CP_WAIT(0); }
        __syncthreads();   // stage s (and Q on iter 0) visible to all

        const float* Ks = sm + OFF_K + s * KT * PA;
        const float* Vs = sm + OFF_V + s * KT * PVt;
        const float* bw = sm + OFF_BW + s * 192;

        // ---- S = Q K^T (warp: 16 rows x 64 cols) ----
        float as_[8][4];
        #pragma unroll
        for (int ni = 0; ni < 8; ++ni)
            #pragma unroll
            for (int e = 0; e < 4; ++e) as_[ni][e] = 0.f;

        #pragma unroll
        for (int ks = 0; ks < 8; ++ks) {
            uint32_t af[4];
            const float* pa = sm + OFF_Q + (mb + q) * PA + ks * 8 + t;
            af[0] = f2tf32(pa[0]);
            af[1] = f2tf32(pa[8 * PA]);
            af[2] = f2tf32(pa[4]);
            af[3] = f2tf32(pa[8 * PA + 4]);
            #pragma unroll
            for (int ni = 0; ni < 8; ++ni) {
                uint32_t bf[2];
                const float* pb = Ks + (ni * 8 + q) * PA + ks * 8 + t;
                bf[0] = f2tf32(pb[0]);
                bf[1] = f2tf32(pb[4]);
                mma_tf32(as_[ni], af, bf);
            }
        }

        // ---- scale + bias; row max ----
        float mx0 = -INFINITY, mx1 = -INFINITY;
        #pragma unroll
        for (int ni = 0; ni < 8; ++ni) {
            const int i0 = ni * 8 + 2 * t - mb - q + 127;  // row mb+q, col ni*8+2t
            as_[ni][0] = fmaf(as_[ni][0], scale, bw[i0]);
            as_[ni][1] = fmaf(as_[ni][1], scale, bw[i0 + 1]);
            as_[ni][2] = fmaf(as_[ni][2], scale, bw[i0 - 8]);
            as_[ni][3] = fmaf(as_[ni][3], scale, bw[i0 - 7]);
            mx0 = fmaxf(mx0, fmaxf(as_[ni][0], as_[ni][1]));
            mx1 = fmaxf(mx1, fmaxf(as_[ni][2], as_[ni][3]));
        }
        #pragma unroll
        for (int off = 1; off <= 2; off <<= 1) {
            mx0 = fmaxf(mx0, __shfl_xor_sync(0xffffffffu, mx0, off));
            mx1 = fmaxf(mx1, __shfl_xor_sync(0xffffffffu, mx1, off));
        }
        const float mn0 = fmaxf(m0, mx0), mn1 = fmaxf(m1, mx1);
        const float c0 = __expf(m0 - mn0), c1 = __expf(m1 - mn1);
        m0 = mn0; m1 = mn1;

        // ---- exp, write P (warp-local rows), row sums ----
        float rs0 = 0.f, rs1 = 0.f;
        #pragma unroll
        for (int ni = 0; ni < 8; ++ni) {
            float p0 = __expf(as_[ni][0] - mn0);
            float p1 = __expf(as_[ni][1] - mn0);
            float p2 = __expf(as_[ni][2] - mn1);
            float p3 = __expf(as_[ni][3] - mn1);
            rs0 += p0 + p1; rs1 += p2 + p3;
            *(float2*)(sm + OFF_P + (mb + q) * PA + ni * 8 + 2 * t)
                = make_float2(p0, p1);
            *(float2*)(sm + OFF_P + (mb + q + 8) * PA + ni * 8 + 2 * t)
                = make_float2(p2, p3);
        }
        #pragma unroll
        for (int off = 1; off <= 2; off <<= 1) {
            rs0 += __shfl_xor_sync(0xffffffffu, rs0, off);
            rs1 += __shfl_xor_sync(0xffffffffu, rs1, off);
        }
        l0 = l0 * c0 + rs0;
        l1 = l1 * c1 + rs1;
        #pragma unroll
        for (int ni = 0; ni < 8; ++ni) {
            ao[ni][0] *= c0; ao[ni][1] *= c0;
            ao[ni][2] *= c1; ao[ni][3] *= c1;
        }
        __syncwarp();      // P visible within warp

        // ---- O += P @ V ----
        #pragma unroll
        for (int ks = 0; ks < 8; ++ks) {
            uint32_t af[4];
            const float* pa = sm + OFF_P + (mb + q) * PA + ks * 8 + t;
            af[0] = f2tf32(pa[0]);
            af[1] = f2tf32(pa[8 * PA]);
            af[2] = f2tf32(pa[4]);
            af[3] = f2tf32(pa[8 * PA + 4]);
            #pragma unroll
            for (int ni = 0; ni < 8; ++ni) {
                uint32_t bf[2];
                const float* pb = Vs + (ks * 8 + t) * PVt + ni * 8 + q;
                bf[0] = f2tf32(pb[0]);
                bf[1] = f2tf32(pb[4 * PVt]);
                mma_tf32(ao[ni], af, bf);
            }
        }

        __syncthreads();   // all warps done reading Ks/Vs[s] before refill
        if (kt + 2 < Tv / KT) { load_kv(kt + 2, s); CP_COMMIT(); }
    }

    // ---- normalize, write out ----
    const float inv0 = 1.f / l0, inv1 = 1.f / l1;
    const int r0 = qbase + mb + q;
    #pragma unroll
    for (int ni = 0; ni < 8; ++ni) {
        const int col = h * HDv + ni * 8 + 2 * t;
        *(float2*)&g_attn[(size_t)(b * Tv + r0) * Dv + col]
            = make_float2(ao[ni][0] * inv0, ao[ni][1] * inv0);
        *(float2*)&g_attn[(size_t)(b * Tv + r0 + 8) * Dv + col]
            = make_float2(ao[ni][2] * inv1, ao[ni][3] * inv1);
    }
}

// ---------------------------------------------------------------------------
// Launcher
// ---------------------------------------------------------------------------
extern "C" void kernel_launch(void* const* d_in, const int* in_sizes, int n_in,
                              void* d_out, int out_size) {
    const float* x       = (const float*)d_in[0];
    const float* qkv_w   = (const float*)d_in[1];
    const float* qkv_b   = (const float*)d_in[2];
    const float* out_w   = (const float*)d_in[3];
    const float* out_b   = (const float*)d_in[4];
    const float* rel_pos = (const float*)d_in[5];
    const float* rpe_w   = (const float*)d_in[6];
    float* out = (float*)d_out;

    float *qkv_p, *attn_p;
    cudaGetSymbolAddress((void**)&qkv_p,  g_qkv);
    cudaGetSymbolAddress((void**)&attn_p, g_attn);

    cudaFuncSetAttribute(tf32_gemm_bias,
                         cudaFuncAttributeMaxDynamicSharedMemorySize, GSM_B);
    cudaFuncSetAttribute(flash_rpe_mma,
                         cudaFuncAttributeMaxDynamicSharedMemorySize, FSM2_BYTES);

    // 1) RPE bias projection
    rpe_bias_kernel<<<NBIAS, 32>>>(rel_pos, rpe_w);

    // 2) QKV projection (tf32 mma.sync)
    {
        dim3 grid(3 * Dv / 128, BT / 128);
        tf32_gemm_bias<<<grid, 256, GSM_B>>>(x, qkv_w, qkv_b, qkv_p,
                                             BT, 3 * Dv, Dv);
    }

    // 3) flash attention with RPE (tf32 mma.sync)
    {
        dim3 grid(Tv / QT, Hv, Bv);
        flash_rpe_mma<<<grid, 256, FSM2_BYTES>>>();
    }

    // 4) output projection (tf32 mma.sync)
    {
        dim3 grid(Dv / 128, BT / 128);
        tf32_gemm_bias<<<grid, 256, GSM_B>>>(attn_p, out_w, out_b, out,
                                             BT, Dv, Dv);
    }
}

// round 6
// speedup vs baseline: 3.2951x; 1.0812x over previous
#include <cuda_runtime.h>
#include <math.h>
#include <stdint.h>

// Problem constants
#define Bv      2
#define Tv      2048
#define Dv      1024
#define Hv      16
#define HDv     64
#define MAXLEN  2048
#define NBIAS   (2 * MAXLEN - 1)   // 4095
#define BT      (Bv * Tv)          // 4096

// ---------------------------------------------------------------------------
// Scratch (device globals)
// ---------------------------------------------------------------------------
__device__ float g_qkv[BT * 3 * Dv];   // [B,T,3,H,HD]  48 MB
__device__ float g_attn[BT * Dv];      // [B,T,H*HD]    16 MB
__device__ float g_bias[4608];         // projected RPE bias (padded from 4095)

// ---------------------------------------------------------------------------
// PTX helpers (sm_103-base safe: cp.async + mma.sync only)
// ---------------------------------------------------------------------------
__device__ __forceinline__ uint32_t smem_u32(const void* p) {
    uint32_t a;
    asm("{ .reg .u64 t; cvta.to.shared.u64 t, %1; cvt.u32.u64 %0, t; }"
        : "=r"(a) : "l"(p));
    return a;
}
__device__ __forceinline__ void cp_async16(uint32_t saddr, const void* gptr) {
    asm volatile("cp.async.cg.shared.global [%0], [%1], 16;"
                 :: "r"(saddr), "l"(gptr) : "memory");
}
#define CP_COMMIT() asm volatile("cp.async.commit_group;" ::: "memory")
#define CP_WAIT(n)  asm volatile("cp.async.wait_group %0;" :: "n"(n) : "memory")

__device__ __forceinline__ uint32_t f2tf32(float f) {
    uint32_t u;
    asm("cvt.rna.tf32.f32 %0, %1;" : "=r"(u) : "f"(f));
    return u;
}
__device__ __forceinline__ void mma_tf32(float c[4], const uint32_t a[4],
                                         const uint32_t b[2]) {
    asm volatile(
        "mma.sync.aligned.m16n8k8.row.col.f32.tf32.tf32.f32 "
        "{%0,%1,%2,%3}, {%4,%5,%6,%7}, {%8,%9}, {%0,%1,%2,%3};"
        : "+f"(c[0]), "+f"(c[1]), "+f"(c[2]), "+f"(c[3])
        : "r"(a[0]), "r"(a[1]), "r"(a[2]), "r"(a[3]),
          "r"(b[0]), "r"(b[1]));
}

// ---------------------------------------------------------------------------
// Kernel 1: bias_vec[j] = rel_pos[j,:] . rpe_w
// ---------------------------------------------------------------------------
__global__ void rpe_bias_kernel(const float* __restrict__ rel_pos,
                                const float* __restrict__ rpe_w) {
    int j = blockIdx.x;
    int lane = threadIdx.x;
    float v = rel_pos[j * HDv + lane] * rpe_w[lane]
            + rel_pos[j * HDv + 32 + lane] * rpe_w[32 + lane];
    #pragma unroll
    for (int o = 16; o > 0; o >>= 1) v += __shfl_xor_sync(0xffffffffu, v, o);
    if (lane == 0) g_bias[j] = v;
}

// ---------------------------------------------------------------------------
// tf32 mma.sync GEMM:  C[M,N] = A[M,K] @ W[N,K]^T + bias[N]
// 128x128 CTA tile, BK=32, 8 warps (2x4), 2-stage cp.async, 2 CTAs/SM.
// rna rounding at fragment load.
// ---------------------------------------------------------------------------
#define BK       32
#define APITCH   36
#define TILE_F   (128 * APITCH)
#define TILE_B   (TILE_F * 4)
#define STG_B    (2 * TILE_B)
#define GSM_B    (2 * STG_B)

__global__ void __launch_bounds__(256, 2)
tf32_gemm_bias(const float* __restrict__ A, const float* __restrict__ W,
               const float* __restrict__ bias, float* __restrict__ C,
               int M, int N, int K) {
    extern __shared__ float smf[];
    const uint32_t sbase = smem_u32(smf);
    const int tid  = threadIdx.x;
    const int wid  = tid >> 5;
    const int lane = tid & 31;
    const int q    = lane >> 2;
    const int t    = lane & 3;
    const int warp_m = wid >> 2;
    const int warp_n = wid & 3;
    const int bm = blockIdx.y * 128;
    const int bn = blockIdx.x * 128;
    const int nchunk = K / BK;

    float acc[4][4][4];
    #pragma unroll
    for (int mi = 0; mi < 4; ++mi)
        #pragma unroll
        for (int ni = 0; ni < 4; ++ni)
            #pragma unroll
            for (int e = 0; e < 4; ++e) acc[mi][ni][e] = 0.f;

    auto load_chunk = [&](int c, int s) {
        const uint32_t ab = sbase + s * STG_B;
        const uint32_t bb = ab + TILE_B;
        #pragma unroll
        for (int i = 0; i < 4; ++i) {
            int idx = tid + 256 * i;
            int row = idx >> 3;
            int c16 = idx & 7;
            uint32_t doff = (uint32_t)(row * (APITCH * 4) + c16 * 16);
            cp_async16(ab + doff, A + (size_t)(bm + row) * K + c * BK + c16 * 4);
            cp_async16(bb + doff, W + (size_t)(bn + row) * K + c * BK + c16 * 4);
        }
    };

    load_chunk(0, 0); CP_COMMIT();
    load_chunk(1, 1); CP_COMMIT();

    for (int c = 0; c < nchunk; ++c) {
        const int s = c & 1;
        if (c + 1 < nchunk) { CP_WAIT(1); } else { CP_WAIT(0); }
        __syncthreads();

        const float* as = smf + s * (STG_B / 4);
        const float* bs = as + TILE_F;
        const int m_base = warp_m * 64;
        const int n_base = warp_n * 32;

        #pragma unroll
        for (int ks = 0; ks < 4; ++ks) {
            const int kc = ks * 8 + t;
            uint32_t af[4][4], bf[4][2];
            #pragma unroll
            for (int mi = 0; mi < 4; ++mi) {
                const float* p = as + (m_base + mi * 16 + q) * APITCH + kc;
                af[mi][0] = f2tf32(p[0]);
                af[mi][2] = f2tf32(p[4]);
                af[mi][1] = f2tf32(p[8 * APITCH]);
                af[mi][3] = f2tf32(p[8 * APITCH + 4]);
            }
            #pragma unroll
            for (int ni = 0; ni < 4; ++ni) {
                const float* p = bs + (n_base + ni * 8 + q) * APITCH + kc;
                bf[ni][0] = f2tf32(p[0]);
                bf[ni][1] = f2tf32(p[4]);
            }
            #pragma unroll
            for (int mi = 0; mi < 4; ++mi)
                #pragma unroll
                for (int ni = 0; ni < 4; ++ni)
                    mma_tf32(acc[mi][ni], af[mi], bf[ni]);
        }

        __syncthreads();
        if (c + 2 < nchunk) { load_chunk(c + 2, s); CP_COMMIT(); }
    }

    #pragma unroll
    for (int mi = 0; mi < 4; ++mi) {
        const int row0 = bm + warp_m * 64 + mi * 16 + q;
        #pragma unroll
        for (int ni = 0; ni < 4; ++ni) {
            const int col = bn + warp_n * 32 + ni * 8 + 2 * t;
            const float b0 = bias[col], b1 = bias[col + 1];
            float2 v0 = make_float2(acc[mi][ni][0] + b0, acc[mi][ni][1] + b1);
            float2 v1 = make_float2(acc[mi][ni][2] + b0, acc[mi][ni][3] + b1);
            *(float2*)&C[(size_t)row0 * N + col] = v0;
            *(float2*)&C[(size_t)(row0 + 8) * N + col] = v1;
        }
    }
}

// ---------------------------------------------------------------------------
// Kernel 3: flash attention with RPE, tf32 mma.sync.
// CTA: 128 q-rows x one (b,h); 8 warps, warp w owns rows [16w,16w+16).
// KT=32 keys/iter (double-buffered) -> smem ~105KB -> 2 CTAs/SM.
// rna rounding: Q and P rounded at smem store; K/V rounded at fragment load.
// ---------------------------------------------------------------------------
#define QT   128
#define KT   32
#define PA   68
#define PVt  72
#define OFF_Q   0
#define OFF_P   (OFF_Q + QT * PA)               // 8704
#define OFF_K   (OFF_P + QT * PA)               // 17408
#define OFF_V   (OFF_K + 2 * KT * PA)           // 21760
#define OFF_BW  (OFF_V + 2 * KT * PVt)          // 26368
#define FSM2_FLOATS (OFF_BW + 2 * 192)          // 26752
#define FSM2_BYTES  (FSM2_FLOATS * 4)           // 107008

__global__ void __launch_bounds__(256, 2)
flash_rpe_mma() {
    extern __shared__ float sm[];
    const uint32_t sb = smem_u32(sm);
    uint32_t* smu = (uint32_t*)sm;
    const int b = blockIdx.z, h = blockIdx.y;
    const int qbase = blockIdx.x * QT;
    const int tid = threadIdx.x, wid = tid >> 5, lane = tid & 31;
    const int q = lane >> 2, t = lane & 3;
    const int mb = wid * 16;
    const float scale = 0.125f;

    // ---- load Q tile, rounded to tf32 (rna) at store ----
    #pragma unroll
    for (int i = 0; i < 8; ++i) {
        int idx = tid + 256 * i;
        int row = idx >> 4;
        int c4  = (idx & 15) * 4;
        float4 v = *(const float4*)&g_qkv[(size_t)(b * Tv + qbase + row) * 3072
                                          + h * HDv + c4];
        uint32_t* p = smu + OFF_Q + row * PA + c4;
        p[0] = f2tf32(v.x); p[1] = f2tf32(v.y);
        p[2] = f2tf32(v.z); p[3] = f2tf32(v.w);
    }

    // ---- K/V/bias loader: chunk kt -> stage s ----
    auto load_kv = [&](int kt, int s) {
        const int kbase = kt * KT;
        const uint32_t kb = sb + (OFF_K + s * KT * PA) * 4;
        const uint32_t vb = sb + (OFF_V + s * KT * PVt) * 4;
        #pragma unroll
        for (int i = 0; i < 2; ++i) {
            int idx = tid + 256 * i;    // 0..511
            int row = idx >> 4;         // 0..31
            int c16 = idx & 15;
            size_t gb = (size_t)(b * Tv + kbase + row) * 3072 + h * HDv + c16 * 4;
            cp_async16(kb + row * (PA * 4)  + c16 * 16, &g_qkv[gb + 1024]);
            cp_async16(vb + row * (PVt * 4) + c16 * 16, &g_qkv[gb + 2048]);
        }
        if (tid < 48) {
            int base = kbase - qbase + 1920;   // 16B aligned
            cp_async16(sb + (OFF_BW + s * 192 + tid * 4) * 4,
                       &g_bias[base + tid * 4]);
        }
    };

    load_kv(0, 0); CP_COMMIT();
    load_kv(1, 1); CP_COMMIT();

    float m0 = -INFINITY, m1 = -INFINITY, l0 = 0.f, l1 = 0.f;
    float ao[8][4];
    #pragma unroll
    for (int ni = 0; ni < 8; ++ni)
        #pragma unroll
        for (int e = 0; e < 4; ++e) ao[ni][e] = 0.f;

    const int NIT = Tv / KT;   // 64
    for (int kt = 0; kt < NIT; ++kt) {
        const int s = kt & 1;
        if (kt < NIT - 1) { CP_WAIT(1); } else { CP_WAIT(0); }
        __syncthreads();

        const float* Ks = sm + OFF_K + s * KT * PA;
        const uint32_t* Vsu = smu + OFF_V + s * KT * PVt;
        const float* bw = sm + OFF_BW + s * 192;

        // ---- S = Q K^T (warp: 16 rows x 32 cols) ----
        float as_[4][4];
        #pragma unroll
        for (int ni = 0; ni < 4; ++ni)
            #pragma unroll
            for (int e = 0; e < 4; ++e) as_[ni][e] = 0.f;

        #pragma unroll
        for (int ks = 0; ks < 8; ++ks) {
            uint32_t af[4];
            const uint32_t* pa = smu + OFF_Q + (mb + q) * PA + ks * 8 + t;
            af[0] = pa[0];                 // pre-rounded at store
            af[1] = pa[8 * PA];
            af[2] = pa[4];
            af[3] = pa[8 * PA + 4];
            #pragma unroll
            for (int ni = 0; ni < 4; ++ni) {
                uint32_t bf[2];
                const float* pb = Ks + (ni * 8 + q) * PA + ks * 8 + t;
                bf[0] = f2tf32(pb[0]);
                bf[1] = f2tf32(pb[4]);
                mma_tf32(as_[ni], af, bf);
            }
        }

        // ---- scale + bias; row max ----
        float mx0 = -INFINITY, mx1 = -INFINITY;
        #pragma unroll
        for (int ni = 0; ni < 4; ++ni) {
            const int i0 = ni * 8 + 2 * t - mb - q + 127;
            as_[ni][0] = fmaf(as_[ni][0], scale, bw[i0]);
            as_[ni][1] = fmaf(as_[ni][1], scale, bw[i0 + 1]);
            as_[ni][2] = fmaf(as_[ni][2], scale, bw[i0 - 8]);
            as_[ni][3] = fmaf(as_[ni][3], scale, bw[i0 - 7]);
            mx0 = fmaxf(mx0, fmaxf(as_[ni][0], as_[ni][1]));
            mx1 = fmaxf(mx1, fmaxf(as_[ni][2], as_[ni][3]));
        }
        #pragma unroll
        for (int off = 1; off <= 2; off <<= 1) {
            mx0 = fmaxf(mx0, __shfl_xor_sync(0xffffffffu, mx0, off));
            mx1 = fmaxf(mx1, __shfl_xor_sync(0xffffffffu, mx1, off));
        }
        const float mn0 = fmaxf(m0, mx0), mn1 = fmaxf(m1, mx1);
        const float c0 = __expf(m0 - mn0), c1 = __expf(m1 - mn1);
        m0 = mn0; m1 = mn1;

        // ---- exp, write P rounded to tf32, row sums ----
        float rs0 = 0.f, rs1 = 0.f;
        #pragma unroll
        for (int ni = 0; ni < 4; ++ni) {
            float p0 = __expf(as_[ni][0] - mn0);
            float p1 = __expf(as_[ni][1] - mn0);
            float p2 = __expf(as_[ni][2] - mn1);
            float p3 = __expf(as_[ni][3] - mn1);
            rs0 += p0 + p1; rs1 += p2 + p3;
            uint32_t* d0 = smu + OFF_P + (mb + q) * PA + ni * 8 + 2 * t;
            uint32_t* d1 = smu + OFF_P + (mb + q + 8) * PA + ni * 8 + 2 * t;
            d0[0] = f2tf32(p0); d0[1] = f2tf32(p1);
            d1[0] = f2tf32(p2); d1[1] = f2tf32(p3);
        }
        #pragma unroll
        for (int off = 1; off <= 2; off <<= 1) {
            rs0 += __shfl_xor_sync(0xffffffffu, rs0, off);
            rs1 += __shfl_xor_sync(0xffffffffu, rs1, off);
        }
        l0 = l0 * c0 + rs0;
        l1 = l1 * c1 + rs1;
        #pragma unroll
        for (int ni = 0; ni < 8; ++ni) {
            ao[ni][0] *= c0; ao[ni][1] *= c0;
            ao[ni][2] *= c1; ao[ni][3] *= c1;
        }
        __syncwarp();      // P visible within warp

        // ---- O += P @ V  (K-dim = 32 keys -> 4 k-steps) ----
        #pragma unroll
        for (int ks = 0; ks < 4; ++ks) {
            uint32_t af[4];
            const uint32_t* pa = smu + OFF_P + (mb + q) * PA + ks * 8 + t;
            af[0] = pa[0];                 // pre-rounded at store
            af[1] = pa[8 * PA];
            af[2] = pa[4];
            af[3] = pa[8 * PA + 4];
            #pragma unroll
            for (int ni = 0; ni < 8; ++ni) {
                uint32_t bf[2];
                const uint32_t* pb = Vsu + (ks * 8 + t) * PVt + ni * 8 + q;
                bf[0] = f2tf32(__uint_as_float(pb[0]));
                bf[1] = f2tf32(__uint_as_float(pb[4 * PVt]));
                mma_tf32(ao[ni], af, bf);
            }
        }

        __syncthreads();   // all warps done with stage s before refill
        if (kt + 2 < NIT) { load_kv(kt + 2, s); CP_COMMIT(); }
    }

    // ---- normalize, write out ----
    const float inv0 = 1.f / l0, inv1 = 1.f / l1;
    const int r0 = qbase + mb + q;
    #pragma unroll
    for (int ni = 0; ni < 8; ++ni) {
        const int col = h * HDv + ni * 8 + 2 * t;
        *(float2*)&g_attn[(size_t)(b * Tv + r0) * Dv + col]
            = make_float2(ao[ni][0] * inv0, ao[ni][1] * inv0);
        *(float2*)&g_attn[(size_t)(b * Tv + r0 + 8) * Dv + col]
            = make_float2(ao[ni][2] * inv1, ao[ni][3] * inv1);
    }
}

// ---------------------------------------------------------------------------
// Launcher
// ---------------------------------------------------------------------------
extern "C" void kernel_launch(void* const* d_in, const int* in_sizes, int n_in,
                              void* d_out, int out_size) {
    const float* x       = (const float*)d_in[0];
    const float* qkv_w   = (const float*)d_in[1];
    const float* qkv_b   = (const float*)d_in[2];
    const float* out_w   = (const float*)d_in[3];
    const float* out_b   = (const float*)d_in[4];
    const float* rel_pos = (const float*)d_in[5];
    const float* rpe_w   = (const float*)d_in[6];
    float* out = (float*)d_out;

    float *qkv_p, *attn_p;
    cudaGetSymbolAddress((void**)&qkv_p,  g_qkv);
    cudaGetSymbolAddress((void**)&attn_p, g_attn);

    cudaFuncSetAttribute(tf32_gemm_bias,
                         cudaFuncAttributeMaxDynamicSharedMemorySize, GSM_B);
    cudaFuncSetAttribute(flash_rpe_mma,
                         cudaFuncAttributeMaxDynamicSharedMemorySize, FSM2_BYTES);

    // 1) RPE bias projection
    rpe_bias_kernel<<<NBIAS, 32>>>(rel_pos, rpe_w);

    // 2) QKV projection (tf32 mma.sync)
    {
        dim3 grid(3 * Dv / 128, BT / 128);
        tf32_gemm_bias<<<grid, 256, GSM_B>>>(x, qkv_w, qkv_b, qkv_p,
                                             BT, 3 * Dv, Dv);
    }

    // 3) flash attention with RPE (tf32 mma.sync)
    {
        dim3 grid(Tv / QT, Hv, Bv);
        flash_rpe_mma<<<grid, 256, FSM2_BYTES>>>();
    }

    // 4) output projection (tf32 mma.sync)
    {
        dim3 grid(Dv / 128, BT / 128);
        tf32_gemm_bias<<<grid, 256, GSM_B>>>(attn_p, out_w, out_b, out,
                                             BT, Dv, Dv);
    }
}

// round 7
// speedup vs baseline: 3.4823x; 1.0568x over previous
#include <cuda_runtime.h>
#include <math.h>
#include <stdint.h>

// Problem constants
#define Bv      2
#define Tv      2048
#define Dv      1024
#define Hv      16
#define HDv     64
#define MAXLEN  2048
#define NBIAS   (2 * MAXLEN - 1)   // 4095
#define BT      (Bv * Tv)          // 4096

// ---------------------------------------------------------------------------
// Scratch (device globals)
// ---------------------------------------------------------------------------
__device__ float g_qkv[BT * 3 * Dv];   // [B,T,3,H,HD] (tf32-rounded)  48 MB
__device__ float g_attn[BT * Dv];      // [B,T,H*HD]   (tf32-rounded)  16 MB
__device__ float g_bias[4608];         // projected RPE bias
__device__ float g_xr[BT * Dv];        // x  pre-rounded       16 MB
__device__ float g_wr[3 * Dv * Dv];    // qkv_w pre-rounded    12 MB
__device__ float g_owr[Dv * Dv];       // out_w pre-rounded     4 MB

// ---------------------------------------------------------------------------
// PTX helpers (sm_103-base safe: cp.async + mma.sync only)
// ---------------------------------------------------------------------------
__device__ __forceinline__ uint32_t smem_u32(const void* p) {
    uint32_t a;
    asm("{ .reg .u64 t; cvta.to.shared.u64 t, %1; cvt.u32.u64 %0, t; }"
        : "=r"(a) : "l"(p));
    return a;
}
__device__ __forceinline__ void cp_async16(uint32_t saddr, const void* gptr) {
    asm volatile("cp.async.cg.shared.global [%0], [%1], 16;"
                 :: "r"(saddr), "l"(gptr) : "memory");
}
#define CP_COMMIT() asm volatile("cp.async.commit_group;" ::: "memory")
#define CP_WAIT(n)  asm volatile("cp.async.wait_group %0;" :: "n"(n) : "memory")

__device__ __forceinline__ uint32_t f2tf32(float f) {
    uint32_t u;
    asm("cvt.rna.tf32.f32 %0, %1;" : "=r"(u) : "f"(f));
    return u;
}
__device__ __forceinline__ float roundtf(float f) {
    return __uint_as_float(f2tf32(f));
}
__device__ __forceinline__ void mma_tf32(float c[4], const uint32_t a[4],
                                         const uint32_t b[2]) {
    asm volatile(
        "mma.sync.aligned.m16n8k8.row.col.f32.tf32.tf32.f32 "
        "{%0,%1,%2,%3}, {%4,%5,%6,%7}, {%8,%9}, {%0,%1,%2,%3};"
        : "+f"(c[0]), "+f"(c[1]), "+f"(c[2]), "+f"(c[3])
        : "r"(a[0]), "r"(a[1]), "r"(a[2]), "r"(a[3]),
          "r"(b[0]), "r"(b[1]));
}

// ---------------------------------------------------------------------------
// Kernel 0: elementwise tf32 pre-round (n multiple of 1024)
// ---------------------------------------------------------------------------
__global__ void round_tf32_kernel(const float* __restrict__ in,
                                  float* __restrict__ out, int n) {
    int i = (blockIdx.x * blockDim.x + threadIdx.x) * 4;
    if (i < n) {
        float4 v = *(const float4*)(in + i);
        v.x = roundtf(v.x); v.y = roundtf(v.y);
        v.z = roundtf(v.z); v.w = roundtf(v.w);
        *(float4*)(out + i) = v;
    }
}

// ---------------------------------------------------------------------------
// Kernel 1: bias_vec[j] = rel_pos[j,:] . rpe_w
// ---------------------------------------------------------------------------
__global__ void rpe_bias_kernel(const float* __restrict__ rel_pos,
                                const float* __restrict__ rpe_w) {
    int j = blockIdx.x;
    int lane = threadIdx.x;
    float v = rel_pos[j * HDv + lane] * rpe_w[lane]
            + rel_pos[j * HDv + 32 + lane] * rpe_w[32 + lane];
    #pragma unroll
    for (int o = 16; o > 0; o >>= 1) v += __shfl_xor_sync(0xffffffffu, v, o);
    if (lane == 0) g_bias[j] = v;
}

// ---------------------------------------------------------------------------
// tf32 mma.sync GEMM: C = A @ W^T + bias. Inputs pre-rounded (raw-bit frags).
// 128x128 CTA tile, BK=32, 8 warps, 3-stage cp.async, 2 CTAs/SM.
// RND: round output to tf32 (for tensors consumed only by later mma).
// ---------------------------------------------------------------------------
#define BK       32
#define APITCH   36
#define TILE_F   (128 * APITCH)
#define TILE_B   (TILE_F * 4)
#define STG_B    (2 * TILE_B)
#define NSTG     3
#define GSM_B    (NSTG * STG_B)           // 110592

template<int RND>
__global__ void __launch_bounds__(256, 2)
tf32_gemm_bias(const float* __restrict__ A, const float* __restrict__ W,
               const float* __restrict__ bias, float* __restrict__ C,
               int M, int N, int K) {
    extern __shared__ float smf[];
    const uint32_t sbase = smem_u32(smf);
    const int tid  = threadIdx.x;
    const int wid  = tid >> 5;
    const int lane = tid & 31;
    const int q    = lane >> 2;
    const int t    = lane & 3;
    const int warp_m = wid >> 2;
    const int warp_n = wid & 3;
    const int bm = blockIdx.y * 128;
    const int bn = blockIdx.x * 128;
    const int nchunk = K / BK;

    float acc[4][4][4];
    #pragma unroll
    for (int mi = 0; mi < 4; ++mi)
        #pragma unroll
        for (int ni = 0; ni < 4; ++ni)
            #pragma unroll
            for (int e = 0; e < 4; ++e) acc[mi][ni][e] = 0.f;

    auto load_chunk = [&](int c, int s) {
        const uint32_t ab = sbase + s * STG_B;
        const uint32_t bb = ab + TILE_B;
        #pragma unroll
        for (int i = 0; i < 4; ++i) {
            int idx = tid + 256 * i;
            int row = idx >> 3;
            int c16 = idx & 7;
            uint32_t doff = (uint32_t)(row * (APITCH * 4) + c16 * 16);
            cp_async16(ab + doff, A + (size_t)(bm + row) * K + c * BK + c16 * 4);
            cp_async16(bb + doff, W + (size_t)(bn + row) * K + c * BK + c16 * 4);
        }
    };

    load_chunk(0, 0); CP_COMMIT();
    load_chunk(1, 1); CP_COMMIT();
    load_chunk(2, 2); CP_COMMIT();

    for (int c = 0; c < nchunk; ++c) {
        const int s = c % NSTG;
        CP_WAIT(2);
        __syncthreads();

        const uint32_t* as = (const uint32_t*)smf + s * (STG_B / 4);
        const uint32_t* bs = as + TILE_F;
        const int m_base = warp_m * 64;
        const int n_base = warp_n * 32;

        #pragma unroll
        for (int ks = 0; ks < 4; ++ks) {
            const int kc = ks * 8 + t;
            uint32_t af[4][4], bf[4][2];
            #pragma unroll
            for (int mi = 0; mi < 4; ++mi) {
                const uint32_t* p = as + (m_base + mi * 16 + q) * APITCH + kc;
                af[mi][0] = p[0];
                af[mi][2] = p[4];
                af[mi][1] = p[8 * APITCH];
                af[mi][3] = p[8 * APITCH + 4];
            }
            #pragma unroll
            for (int ni = 0; ni < 4; ++ni) {
                const uint32_t* p = bs + (n_base + ni * 8 + q) * APITCH + kc;
                bf[ni][0] = p[0];
                bf[ni][1] = p[4];
            }
            #pragma unroll
            for (int mi = 0; mi < 4; ++mi)
                #pragma unroll
                for (int ni = 0; ni < 4; ++ni)
                    mma_tf32(acc[mi][ni], af[mi], bf[ni]);
        }

        __syncthreads();
        if (c + NSTG < nchunk) load_chunk(c + NSTG, s);
        CP_COMMIT();   // uniform group accounting (possibly empty)
    }

    #pragma unroll
    for (int mi = 0; mi < 4; ++mi) {
        const int row0 = bm + warp_m * 64 + mi * 16 + q;
        #pragma unroll
        for (int ni = 0; ni < 4; ++ni) {
            const int col = bn + warp_n * 32 + ni * 8 + 2 * t;
            const float b0 = bias[col], b1 = bias[col + 1];
            float o00 = acc[mi][ni][0] + b0, o01 = acc[mi][ni][1] + b1;
            float o10 = acc[mi][ni][2] + b0, o11 = acc[mi][ni][3] + b1;
            if (RND) {
                o00 = roundtf(o00); o01 = roundtf(o01);
                o10 = roundtf(o10); o11 = roundtf(o11);
            }
            *(float2*)&C[(size_t)row0 * N + col] = make_float2(o00, o01);
            *(float2*)&C[(size_t)(row0 + 8) * N + col] = make_float2(o10, o11);
        }
    }
}

// ---------------------------------------------------------------------------
// Kernel 3: flash attention with RPE, tf32 mma.sync.
// Inputs (g_qkv) pre-rounded -> raw-bit Q/K/V fragments, zero cvt in mainloop.
// CTA: 128 q-rows x one (b,h); 8 warps; KT=32 double-buffered; 2 CTAs/SM.
// ---------------------------------------------------------------------------
#define QT   128
#define KT   32
#define PA   68
#define PVt  72
#define OFF_Q   0
#define OFF_P   (OFF_Q + QT * PA)               // 8704
#define OFF_K   (OFF_P + QT * PA)               // 17408
#define OFF_V   (OFF_K + 2 * KT * PA)           // 21760
#define OFF_BW  (OFF_V + 2 * KT * PVt)          // 26368
#define FSM2_FLOATS (OFF_BW + 2 * 192)          // 26752
#define FSM2_BYTES  (FSM2_FLOATS * 4)           // 107008

__global__ void __launch_bounds__(256, 2)
flash_rpe_mma() {
    extern __shared__ float sm[];
    const uint32_t sb = smem_u32(sm);
    uint32_t* smu = (uint32_t*)sm;
    const int b = blockIdx.z, h = blockIdx.y;
    const int qbase = blockIdx.x * QT;
    const int tid = threadIdx.x, wid = tid >> 5, lane = tid & 31;
    const int q = lane >> 2, t = lane & 3;
    const int mb = wid * 16;
    const float scale = 0.125f;

    // ---- load Q tile (already tf32-rounded in g_qkv) ----
    #pragma unroll
    for (int i = 0; i < 8; ++i) {
        int idx = tid + 256 * i;
        int row = idx >> 4;
        int c4  = (idx & 15) * 4;
        float4 v = *(const float4*)&g_qkv[(size_t)(b * Tv + qbase + row) * 3072
                                          + h * HDv + c4];
        float* p = sm + OFF_Q + row * PA + c4;
        p[0] = v.x; p[1] = v.y; p[2] = v.z; p[3] = v.w;
    }

    // ---- K/V/bias loader: chunk kt -> stage s ----
    auto load_kv = [&](int kt, int s) {
        const int kbase = kt * KT;
        const uint32_t kb = sb + (OFF_K + s * KT * PA) * 4;
        const uint32_t vb = sb + (OFF_V + s * KT * PVt) * 4;
        #pragma unroll
        for (int i = 0; i < 2; ++i) {
            int idx = tid + 256 * i;    // 0..511
            int row = idx >> 4;         // 0..31
            int c16 = idx & 15;
            size_t gb = (size_t)(b * Tv + kbase + row) * 3072 + h * HDv + c16 * 4;
            cp_async16(kb + row * (PA * 4)  + c16 * 16, &g_qkv[gb + 1024]);
            cp_async16(vb + row * (PVt * 4) + c16 * 16, &g_qkv[gb + 2048]);
        }
        if (tid < 48) {
            int base = kbase - qbase + 1920;   // 16B aligned
            cp_async16(sb + (OFF_BW + s * 192 + tid * 4) * 4,
                       &g_bias[base + tid * 4]);
        }
    };

    load_kv(0, 0); CP_COMMIT();
    load_kv(1, 1); CP_COMMIT();

    float m0 = -INFINITY, m1 = -INFINITY, l0 = 0.f, l1 = 0.f;
    float ao[8][4];
    #pragma unroll
    for (int ni = 0; ni < 8; ++ni)
        #pragma unroll
        for (int e = 0; e < 4; ++e) ao[ni][e] = 0.f;

    const int NIT = Tv / KT;   // 64
    for (int kt = 0; kt < NIT; ++kt) {
        const int s = kt & 1;
        if (kt < NIT - 1) { CP_WAIT(1); } else { CP_WAIT(0); }
        __syncthreads();

        const uint32_t* Ksu = smu + OFF_K + s * KT * PA;
        const uint32_t* Vsu = smu + OFF_V + s * KT * PVt;
        const float* bw = sm + OFF_BW + s * 192;

        // ---- S = Q K^T (warp: 16 rows x 32 cols), raw-bit frags ----
        float as_[4][4];
        #pragma unroll
        for (int ni = 0; ni < 4; ++ni)
            #pragma unroll
            for (int e = 0; e < 4; ++e) as_[ni][e] = 0.f;

        #pragma unroll
        for (int ks = 0; ks < 8; ++ks) {
            uint32_t af[4];
            const uint32_t* pa = smu + OFF_Q + (mb + q) * PA + ks * 8 + t;
            af[0] = pa[0];
            af[1] = pa[8 * PA];
            af[2] = pa[4];
            af[3] = pa[8 * PA + 4];
            #pragma unroll
            for (int ni = 0; ni < 4; ++ni) {
                uint32_t bf[2];
                const uint32_t* pb = Ksu + (ni * 8 + q) * PA + ks * 8 + t;
                bf[0] = pb[0];
                bf[1] = pb[4];
                mma_tf32(as_[ni], af, bf);
            }
        }

        // ---- scale + bias; row max ----
        float mx0 = -INFINITY, mx1 = -INFINITY;
        #pragma unroll
        for (int ni = 0; ni < 4; ++ni) {
            const int i0 = ni * 8 + 2 * t - mb - q + 127;
            as_[ni][0] = fmaf(as_[ni][0], scale, bw[i0]);
            as_[ni][1] = fmaf(as_[ni][1], scale, bw[i0 + 1]);
            as_[ni][2] = fmaf(as_[ni][2], scale, bw[i0 - 8]);
            as_[ni][3] = fmaf(as_[ni][3], scale, bw[i0 - 7]);
            mx0 = fmaxf(mx0, fmaxf(as_[ni][0], as_[ni][1]));
            mx1 = fmaxf(mx1, fmaxf(as_[ni][2], as_[ni][3]));
        }
        #pragma unroll
        for (int off = 1; off <= 2; off <<= 1) {
            mx0 = fmaxf(mx0, __shfl_xor_sync(0xffffffffu, mx0, off));
            mx1 = fmaxf(mx1, __shfl_xor_sync(0xffffffffu, mx1, off));
        }
        const float mn0 = fmaxf(m0, mx0), mn1 = fmaxf(m1, mx1);
        const float c0 = __expf(m0 - mn0), c1 = __expf(m1 - mn1);
        m0 = mn0; m1 = mn1;

        // ---- exp, write P rounded to tf32, row sums ----
        float rs0 = 0.f, rs1 = 0.f;
        #pragma unroll
        for (int ni = 0; ni < 4; ++ni) {
            float p0 = __expf(as_[ni][0] - mn0);
            float p1 = __expf(as_[ni][1] - mn0);
            float p2 = __expf(as_[ni][2] - mn1);
            float p3 = __expf(as_[ni][3] - mn1);
            rs0 += p0 + p1; rs1 += p2 + p3;
            uint32_t* d0 = smu + OFF_P + (mb + q) * PA + ni * 8 + 2 * t;
            uint32_t* d1 = smu + OFF_P + (mb + q + 8) * PA + ni * 8 + 2 * t;
            d0[0] = f2tf32(p0); d0[1] = f2tf32(p1);
            d1[0] = f2tf32(p2); d1[1] = f2tf32(p3);
        }
        #pragma unroll
        for (int off = 1; off <= 2; off <<= 1) {
            rs0 += __shfl_xor_sync(0xffffffffu, rs0, off);
            rs1 += __shfl_xor_sync(0xffffffffu, rs1, off);
        }
        l0 = l0 * c0 + rs0;
        l1 = l1 * c1 + rs1;
        #pragma unroll
        for (int ni = 0; ni < 8; ++ni) {
            ao[ni][0] *= c0; ao[ni][1] *= c0;
            ao[ni][2] *= c1; ao[ni][3] *= c1;
        }
        __syncwarp();      // P visible within warp

        // ---- O += P @ V  (raw-bit V frags) ----
        #pragma unroll
        for (int ks = 0; ks < 4; ++ks) {
            uint32_t af[4];
            const uint32_t* pa = smu + OFF_P + (mb + q) * PA + ks * 8 + t;
            af[0] = pa[0];
            af[1] = pa[8 * PA];
            af[2] = pa[4];
            af[3] = pa[8 * PA + 4];
            #pragma unroll
            for (int ni = 0; ni < 8; ++ni) {
                uint32_t bf[2];
                const uint32_t* pb = Vsu + (ks * 8 + t) * PVt + ni * 8 + q;
                bf[0] = pb[0];
                bf[1] = pb[4 * PVt];
                mma_tf32(ao[ni], af, bf);
            }
        }

        __syncthreads();   // all warps done with stage s before refill
        if (kt + 2 < NIT) { load_kv(kt + 2, s); CP_COMMIT(); }
    }

    // ---- normalize, round (out-proj consumes via mma), write out ----
    const float inv0 = 1.f / l0, inv1 = 1.f / l1;
    const int r0 = qbase + mb + q;
    #pragma unroll
    for (int ni = 0; ni < 8; ++ni) {
        const int col = h * HDv + ni * 8 + 2 * t;
        *(float2*)&g_attn[(size_t)(b * Tv + r0) * Dv + col]
            = make_float2(roundtf(ao[ni][0] * inv0), roundtf(ao[ni][1] * inv0));
        *(float2*)&g_attn[(size_t)(b * Tv + r0 + 8) * Dv + col]
            = make_float2(roundtf(ao[ni][2] * inv1), roundtf(ao[ni][3] * inv1));
    }
}

// ---------------------------------------------------------------------------
// Launcher
// ---------------------------------------------------------------------------
extern "C" void kernel_launch(void* const* d_in, const int* in_sizes, int n_in,
                              void* d_out, int out_size) {
    const float* x       = (const float*)d_in[0];
    const float* qkv_w   = (const float*)d_in[1];
    const float* qkv_b   = (const float*)d_in[2];
    const float* out_w   = (const float*)d_in[3];
    const float* out_b   = (const float*)d_in[4];
    const float* rel_pos = (const float*)d_in[5];
    const float* rpe_w   = (const float*)d_in[6];
    float* out = (float*)d_out;

    float *qkv_p, *attn_p, *xr_p, *wr_p, *owr_p;
    cudaGetSymbolAddress((void**)&qkv_p,  g_qkv);
    cudaGetSymbolAddress((void**)&attn_p, g_attn);
    cudaGetSymbolAddress((void**)&xr_p,   g_xr);
    cudaGetSymbolAddress((void**)&wr_p,   g_wr);
    cudaGetSymbolAddress((void**)&owr_p,  g_owr);

    cudaFuncSetAttribute(tf32_gemm_bias<1>,
                         cudaFuncAttributeMaxDynamicSharedMemorySize, GSM_B);
    cudaFuncSetAttribute(tf32_gemm_bias<0>,
                         cudaFuncAttributeMaxDynamicSharedMemorySize, GSM_B);
    cudaFuncSetAttribute(flash_rpe_mma,
                         cudaFuncAttributeMaxDynamicSharedMemorySize, FSM2_BYTES);

    // 0) pre-round mma inputs to tf32 (rna)
    round_tf32_kernel<<<BT * Dv / 1024, 256>>>(x, xr_p, BT * Dv);
    round_tf32_kernel<<<3 * Dv * Dv / 1024, 256>>>(qkv_w, wr_p, 3 * Dv * Dv);
    round_tf32_kernel<<<Dv * Dv / 1024, 256>>>(out_w, owr_p, Dv * Dv);

    // 1) RPE bias projection
    rpe_bias_kernel<<<NBIAS, 32>>>(rel_pos, rpe_w);

    // 2) QKV projection (raw-bit tf32 mma, rounded output)
    {
        dim3 grid(3 * Dv / 128, BT / 128);
        tf32_gemm_bias<1><<<grid, 256, GSM_B>>>(xr_p, wr_p, qkv_b, qkv_p,
                                                BT, 3 * Dv, Dv);
    }

    // 3) flash attention with RPE (zero-cvt mainloop)
    {
        dim3 grid(Tv / QT, Hv, Bv);
        flash_rpe_mma<<<grid, 256, FSM2_BYTES>>>();
    }

    // 4) output projection (raw-bit tf32 mma, fp32 output)
    {
        dim3 grid(Dv / 128, BT / 128);
        tf32_gemm_bias<0><<<grid, 256, GSM_B>>>(attn_p, owr_p, out_b, out,
                                                BT, Dv, Dv);
    }
}

// round 8
// speedup vs baseline: 5.8883x; 1.6909x over previous
#include <cuda_runtime.h>
#include <cuda_fp16.h>
#include <math.h>
#include <stdint.h>

// Problem constants
#define Bv      2
#define Tv      2048
#define Dv      1024
#define Hv      16
#define HDv     64
#define MAXLEN  2048
#define NBIAS   (2 * MAXLEN - 1)   // 4095
#define BT      (Bv * Tv)          // 4096

// ---------------------------------------------------------------------------
// Scratch (device globals)
// ---------------------------------------------------------------------------
__device__ float  g_bias[4608];           // projected RPE bias (zero-padded)
__device__ __half g_xh[BT * Dv];          // x      (half)
__device__ __half g_wh[3 * Dv * Dv];      // qkv_w  (half)
__device__ __half g_owh[Dv * Dv];         // out_w  (half)
__device__ __half g_qh[BT * Dv];          // Q      [b*T+t][h*64+d]
__device__ __half g_kh[BT * Dv];          // K      [b*T+t][h*64+d]
__device__ __half g_vT[Bv * Hv * HDv * Tv]; // V^T  [(b*16+h)*64+d][token]
__device__ __half g_attnh[BT * Dv];       // attention output (half)

// ---------------------------------------------------------------------------
// PTX helpers (sm_103-base safe: cp.async + mma.sync only)
// ---------------------------------------------------------------------------
__device__ __forceinline__ uint32_t smem_u32(const void* p) {
    uint32_t a;
    asm("{ .reg .u64 t; cvta.to.shared.u64 t, %1; cvt.u32.u64 %0, t; }"
        : "=r"(a) : "l"(p));
    return a;
}
__device__ __forceinline__ void cp_async16(uint32_t saddr, const void* gptr) {
    asm volatile("cp.async.cg.shared.global [%0], [%1], 16;"
                 :: "r"(saddr), "l"(gptr) : "memory");
}
#define CP_COMMIT() asm volatile("cp.async.commit_group;" ::: "memory")
#define CP_WAIT(n)  asm volatile("cp.async.wait_group %0;" :: "n"(n) : "memory")

__device__ __forceinline__ void mma_f16(float c[4], const uint32_t a[4],
                                        const uint32_t b[2]) {
    asm volatile(
        "mma.sync.aligned.m16n8k16.row.col.f32.f16.f16.f32 "
        "{%0,%1,%2,%3}, {%4,%5,%6,%7}, {%8,%9}, {%0,%1,%2,%3};"
        : "+f"(c[0]), "+f"(c[1]), "+f"(c[2]), "+f"(c[3])
        : "r"(a[0]), "r"(a[1]), "r"(a[2]), "r"(a[3]),
          "r"(b[0]), "r"(b[1]));
}
__device__ __forceinline__ uint32_t pack_h2(float lo, float hi) {
    __half2 h = __floats2half2_rn(lo, hi);
    return *(uint32_t*)&h;
}

// ---------------------------------------------------------------------------
// Kernel 0: fp32 -> fp16 convert (n multiple of 1024)
// ---------------------------------------------------------------------------
__global__ void cvt_half_kernel(const float* __restrict__ in,
                                __half* __restrict__ out, int n) {
    int i = (blockIdx.x * blockDim.x + threadIdx.x) * 4;
    if (i < n) {
        float4 v = *(const float4*)(in + i);
        uint2 o;
        o.x = pack_h2(v.x, v.y);
        o.y = pack_h2(v.z, v.w);
        *(uint2*)&out[i] = o;
    }
}

// ---------------------------------------------------------------------------
// Kernel 1: bias_vec[j] = rel_pos[j,:] . rpe_w   (8 warps/block)
// ---------------------------------------------------------------------------
__global__ void rpe_bias_kernel(const float* __restrict__ rel_pos,
                                const float* __restrict__ rpe_w) {
    int wid = threadIdx.x >> 5, lane = threadIdx.x & 31;
    int j = blockIdx.x * 8 + wid;
    if (j >= NBIAS) return;
    float v = rel_pos[j * HDv + lane] * rpe_w[lane]
            + rel_pos[j * HDv + 32 + lane] * rpe_w[32 + lane];
    #pragma unroll
    for (int o = 16; o > 0; o >>= 1) v += __shfl_xor_sync(0xffffffffu, v, o);
    if (lane == 0) g_bias[j] = v;
}

// ---------------------------------------------------------------------------
// fp16 mma.sync GEMM: C = A(half) @ W(half)^T + bias(fp32)
// 128x128 CTA tile, BK=32 halfs, 8 warps (2x4), 4-stage cp.async, 2 CTAs/SM.
// MODE 0: float output (final out-proj)
// MODE 1: QKV output: Q,K -> half [token][1024]; V -> transposed half scatter
// ---------------------------------------------------------------------------
#define BKH    32                      // halfs per K-chunk
#define PAG    20                      // u32 pitch per row (16 data + 4 pad)
#define TILEU  (128 * PAG)             // 2560 u32 per operand tile
#define STGU   (2 * TILEU)             // 5120 u32 per stage
#define GNSTG  4
#define GSM_B  (GNSTG * STGU * 4)      // 81920 bytes

template<int MODE>
__global__ void __launch_bounds__(256, 2)
f16_gemm(const __half* __restrict__ A, const __half* __restrict__ W,
         const float* __restrict__ bias, float* __restrict__ Cf,
         __half* __restrict__ qh, __half* __restrict__ kh,
         __half* __restrict__ vT, int M, int N, int K) {
    extern __shared__ uint32_t smu[];
    const uint32_t sbase = smem_u32(smu);
    const int tid  = threadIdx.x;
    const int wid  = tid >> 5;
    const int lane = tid & 31;
    const int q    = lane >> 2;
    const int t    = lane & 3;
    const int warp_m = wid >> 2;
    const int warp_n = wid & 3;
    const int bm = blockIdx.y * 128;
    const int bn = blockIdx.x * 128;
    const int nchunk = K / BKH;        // 32

    float acc[4][4][4];
    #pragma unroll
    for (int mi = 0; mi < 4; ++mi)
        #pragma unroll
        for (int ni = 0; ni < 4; ++ni)
            #pragma unroll
            for (int e = 0; e < 4; ++e) acc[mi][ni][e] = 0.f;

    auto load_chunk = [&](int c, int s) {
        const uint32_t ab = sbase + s * (STGU * 4);
        const uint32_t bb = ab + TILEU * 4;
        #pragma unroll
        for (int i = 0; i < 2; ++i) {
            int idx = tid + 256 * i;       // 0..511
            int row = idx >> 2;            // 0..127
            int cc  = idx & 3;             // 16B chunk within row
            uint32_t doff = (uint32_t)(row * PAG + cc * 4) * 4;
            cp_async16(ab + doff, A + (size_t)(bm + row) * K + c * BKH + cc * 8);
            cp_async16(bb + doff, W + (size_t)(bn + row) * K + c * BKH + cc * 8);
        }
    };

    load_chunk(0, 0); CP_COMMIT();
    load_chunk(1, 1); CP_COMMIT();
    load_chunk(2, 2); CP_COMMIT();

    for (int c = 0; c < nchunk; ++c) {
        const int s = c & 3;
        CP_WAIT(2);
        __syncthreads();

        const uint32_t* as = smu + s * STGU;
        const uint32_t* bs = as + TILEU;
        const int m_base = warp_m * 64;
        const int n_base = warp_n * 32;

        #pragma unroll
        for (int ks = 0; ks < 2; ++ks) {
            uint32_t af[4][4], bf[4][2];
            #pragma unroll
            for (int mi = 0; mi < 4; ++mi) {
                const uint32_t* p = as + (m_base + mi * 16 + q) * PAG + ks * 8 + t;
                af[mi][0] = p[0];
                af[mi][1] = p[8 * PAG];
                af[mi][2] = p[4];
                af[mi][3] = p[8 * PAG + 4];
            }
            #pragma unroll
            for (int ni = 0; ni < 4; ++ni) {
                const uint32_t* p = bs + (n_base + ni * 8 + q) * PAG + ks * 8 + t;
                bf[ni][0] = p[0];
                bf[ni][1] = p[4];
            }
            #pragma unroll
            for (int mi = 0; mi < 4; ++mi)
                #pragma unroll
                for (int ni = 0; ni < 4; ++ni)
                    mma_f16(acc[mi][ni], af[mi], bf[ni]);
        }

        __syncthreads();
        if (c + 3 < nchunk) load_chunk(c + 3, (c + 3) & 3);
        CP_COMMIT();   // uniform group accounting
    }

    #pragma unroll
    for (int mi = 0; mi < 4; ++mi) {
        const int row0 = bm + warp_m * 64 + mi * 16 + q;
        #pragma unroll
        for (int ni = 0; ni < 4; ++ni) {
            const int col = bn + warp_n * 32 + ni * 8 + 2 * t;
            const float b0 = bias[col], b1 = bias[col + 1];
            float o00 = acc[mi][ni][0] + b0, o01 = acc[mi][ni][1] + b1;
            float o10 = acc[mi][ni][2] + b0, o11 = acc[mi][ni][3] + b1;
            if (MODE == 0) {
                *(float2*)&Cf[(size_t)row0 * N + col] = make_float2(o00, o01);
                *(float2*)&Cf[(size_t)(row0 + 8) * N + col] = make_float2(o10, o11);
            } else {
                if (bn < 2048) {
                    __half* dst = (bn < 1024) ? qh : kh;
                    int coln = (bn < 1024) ? col : col - 1024;
                    *(uint32_t*)&dst[(size_t)row0 * 1024 + coln] = pack_h2(o00, o01);
                    *(uint32_t*)&dst[(size_t)(row0 + 8) * 1024 + coln] = pack_h2(o10, o11);
                } else {
                    int hd = col - 2048;
                    int h = hd >> 6, d = hd & 63;
                    int bb = row0 >> 11, token = row0 & 2047;
                    __half* base = vT + ((size_t)((bb * 16 + h) * 64 + d)) * 2048 + token;
                    base[0]        = __float2half_rn(o00);
                    base[2048]     = __float2half_rn(o01);
                    base[8]        = __float2half_rn(o10);
                    base[2048 + 8] = __float2half_rn(o11);
                }
            }
        }
    }
}

// ---------------------------------------------------------------------------
// Kernel 3: flash attention with RPE, fp16 mma.sync.
// CTA: 128 q-rows x one (b,h); 8 warps, warp w owns rows [16w,16w+16).
// KT=32 keys/iter double-buffered. P stays in registers (no smem round-trip).
// ---------------------------------------------------------------------------
#define QT    128
#define KT    32
#define QPA   36                         // u32 pitch, Q/K rows (32 data + 4)
#define VPA   20                         // u32 pitch, V^T rows (16 data + 4)
#define OFF_Q   0                        // 128*36 = 4608 u32
#define OFF_K   (OFF_Q + QT * QPA)       // 2 * 32*36 = 2304
#define OFF_V   (OFF_K + 2 * KT * QPA)   // 2 * 64*20 = 2560
#define OFF_BW  (OFF_V + 2 * HDv * VPA)  // 2 * 192 fp32
#define FSMU    (OFF_BW + 2 * 192)       // 9856 u32
#define FSM_B   (FSMU * 4)               // 39424 bytes

__global__ void __launch_bounds__(256, 2)
flash_rpe_f16() {
    extern __shared__ uint32_t smu[];
    const uint32_t sb = smem_u32(smu);
    float* smf = (float*)smu;
    const int b = blockIdx.z, h = blockIdx.y;
    const int qbase = blockIdx.x * QT;
    const int tid = threadIdx.x, wid = tid >> 5, lane = tid & 31;
    const int q = lane >> 2, t = lane & 3;
    const int mb = wid * 16;
    const float scale = 0.125f;

    // ---- Q tile via cp.async (group 0, together with kv0) ----
    {
        #pragma unroll
        for (int i = 0; i < 4; ++i) {
            int idx = tid + 256 * i;          // 0..1023
            int row = idx >> 3;               // 0..127
            int c8  = idx & 7;
            cp_async16(sb + (uint32_t)(OFF_Q + row * QPA + c8 * 4) * 4,
                       g_qh + (size_t)(b * Tv + qbase + row) * 1024 + h * 64 + c8 * 8);
        }
    }

    auto load_kv = [&](int kt, int s) {
        const int kbase = kt * KT;
        const uint32_t kb = sb + (uint32_t)(OFF_K + s * KT * QPA) * 4;
        const uint32_t vb = sb + (uint32_t)(OFF_V + s * HDv * VPA) * 4;
        {   // K: 32 rows x 8 chunks = 256
            int row = tid >> 3, c8 = tid & 7;
            cp_async16(kb + (uint32_t)(row * QPA + c8 * 4) * 4,
                       g_kh + (size_t)(b * Tv + kbase + row) * 1024 + h * 64 + c8 * 8);
        }
        {   // V^T: 64 rows x 4 chunks = 256
            int row = tid >> 2, c4 = tid & 3;
            cp_async16(vb + (uint32_t)(row * VPA + c4 * 4) * 4,
                       g_vT + (size_t)((b * 16 + h) * 64 + row) * 2048 + kbase + c4 * 8);
        }
        if (tid < 48) {
            int base = kbase - qbase + 1920;   // 16B aligned
            cp_async16(sb + (uint32_t)(OFF_BW + s * 192 + tid * 4) * 4,
                       &g_bias[base + tid * 4]);
        }
    };

    load_kv(0, 0); CP_COMMIT();
    load_kv(1, 1); CP_COMMIT();

    float m0 = -INFINITY, m1 = -INFINITY, l0 = 0.f, l1 = 0.f;
    float ao[8][4];
    #pragma unroll
    for (int ni = 0; ni < 8; ++ni)
        #pragma unroll
        for (int e = 0; e < 4; ++e) ao[ni][e] = 0.f;

    const int NIT = Tv / KT;   // 64
    for (int kt = 0; kt < NIT; ++kt) {
        const int s = kt & 1;
        if (kt < NIT - 1) { CP_WAIT(1); } else { CP_WAIT(0); }
        __syncthreads();

        const uint32_t* Ksu = smu + OFF_K + s * KT * QPA;
        const uint32_t* Vsu = smu + OFF_V + s * HDv * VPA;
        const float* bw = smf + OFF_BW + s * 192;

        // ---- S = Q K^T (warp: 16 rows x 32 cols), d-contraction 4 k-steps ----
        float as_[4][4];
        #pragma unroll
        for (int ni = 0; ni < 4; ++ni)
            #pragma unroll
            for (int e = 0; e < 4; ++e) as_[ni][e] = 0.f;

        #pragma unroll
        for (int ks = 0; ks < 4; ++ks) {
            uint32_t af[4];
            const uint32_t* pa = smu + OFF_Q + (mb + q) * QPA + ks * 8 + t;
            af[0] = pa[0];
            af[1] = pa[8 * QPA];
            af[2] = pa[4];
            af[3] = pa[8 * QPA + 4];
            #pragma unroll
            for (int ni = 0; ni < 4; ++ni) {
                uint32_t bf[2];
                const uint32_t* pb = Ksu + (ni * 8 + q) * QPA + ks * 8 + t;
                bf[0] = pb[0];
                bf[1] = pb[4];
                mma_f16(as_[ni], af, bf);
            }
        }

        // ---- scale + bias; row max ----
        float mx0 = -INFINITY, mx1 = -INFINITY;
        #pragma unroll
        for (int ni = 0; ni < 4; ++ni) {
            const int i0 = ni * 8 + 2 * t - mb - q + 127;
            as_[ni][0] = fmaf(as_[ni][0], scale, bw[i0]);
            as_[ni][1] = fmaf(as_[ni][1], scale, bw[i0 + 1]);
            as_[ni][2] = fmaf(as_[ni][2], scale, bw[i0 - 8]);
            as_[ni][3] = fmaf(as_[ni][3], scale, bw[i0 - 7]);
            mx0 = fmaxf(mx0, fmaxf(as_[ni][0], as_[ni][1]));
            mx1 = fmaxf(mx1, fmaxf(as_[ni][2], as_[ni][3]));
        }
        #pragma unroll
        for (int off = 1; off <= 2; off <<= 1) {
            mx0 = fmaxf(mx0, __shfl_xor_sync(0xffffffffu, mx0, off));
            mx1 = fmaxf(mx1, __shfl_xor_sync(0xffffffffu, mx1, off));
        }
        const float mn0 = fmaxf(m0, mx0), mn1 = fmaxf(m1, mx1);
        const float c0 = __expf(m0 - mn0), c1 = __expf(m1 - mn1);
        m0 = mn0; m1 = mn1;

        // ---- exp; P packed to half2 IN REGISTERS; row sums ----
        float rs0 = 0.f, rs1 = 0.f;
        uint32_t pf[4][2];
        #pragma unroll
        for (int ni = 0; ni < 4; ++ni) {
            float p0 = __expf(as_[ni][0] - mn0);
            float p1 = __expf(as_[ni][1] - mn0);
            float p2 = __expf(as_[ni][2] - mn1);
            float p3 = __expf(as_[ni][3] - mn1);
            rs0 += p0 + p1; rs1 += p2 + p3;
            pf[ni][0] = pack_h2(p0, p1);   // row q
            pf[ni][1] = pack_h2(p2, p3);   // row q+8
        }
        #pragma unroll
        for (int off = 1; off <= 2; off <<= 1) {
            rs0 += __shfl_xor_sync(0xffffffffu, rs0, off);
            rs1 += __shfl_xor_sync(0xffffffffu, rs1, off);
        }
        l0 = l0 * c0 + rs0;
        l1 = l1 * c1 + rs1;
        #pragma unroll
        for (int ni = 0; ni < 8; ++ni) {
            ao[ni][0] *= c0; ao[ni][1] *= c0;
            ao[ni][2] *= c1; ao[ni][3] *= c1;
        }

        // ---- O += P @ V : A-frags from pf (thread-local), B from V^T ----
        #pragma unroll
        for (int ks = 0; ks < 2; ++ks) {
            uint32_t af[4];
            af[0] = pf[2 * ks][0];
            af[1] = pf[2 * ks][1];
            af[2] = pf[2 * ks + 1][0];
            af[3] = pf[2 * ks + 1][1];
            #pragma unroll
            for (int ni = 0; ni < 8; ++ni) {
                uint32_t bf[2];
                const uint32_t* pb = Vsu + (ni * 8 + q) * VPA + ks * 8 + t;
                bf[0] = pb[0];
                bf[1] = pb[4];
                mma_f16(ao[ni], af, bf);
            }
        }

        __syncthreads();   // all warps done with stage s before refill
        if (kt + 2 < NIT) { load_kv(kt + 2, s); CP_COMMIT(); }
    }

    // ---- normalize, write half attn ----
    const float inv0 = 1.f / l0, inv1 = 1.f / l1;
    const int r0 = qbase + mb + q;
    #pragma unroll
    for (int ni = 0; ni < 8; ++ni) {
        const int col = h * HDv + ni * 8 + 2 * t;
        *(uint32_t*)&g_attnh[(size_t)(b * Tv + r0) * Dv + col]
            = pack_h2(ao[ni][0] * inv0, ao[ni][1] * inv0);
        *(uint32_t*)&g_attnh[(size_t)(b * Tv + r0 + 8) * Dv + col]
            = pack_h2(ao[ni][2] * inv1, ao[ni][3] * inv1);
    }
}

// ---------------------------------------------------------------------------
// Launcher
// ---------------------------------------------------------------------------
extern "C" void kernel_launch(void* const* d_in, const int* in_sizes, int n_in,
                              void* d_out, int out_size) {
    const float* x       = (const float*)d_in[0];
    const float* qkv_w   = (const float*)d_in[1];
    const float* qkv_b   = (const float*)d_in[2];
    const float* out_w   = (const float*)d_in[3];
    const float* out_b   = (const float*)d_in[4];
    const float* rel_pos = (const float*)d_in[5];
    const float* rpe_w   = (const float*)d_in[6];
    float* out = (float*)d_out;

    __half *xh, *wh, *owh, *qh, *kh, *vT, *attnh;
    cudaGetSymbolAddress((void**)&xh,    g_xh);
    cudaGetSymbolAddress((void**)&wh,    g_wh);
    cudaGetSymbolAddress((void**)&owh,   g_owh);
    cudaGetSymbolAddress((void**)&qh,    g_qh);
    cudaGetSymbolAddress((void**)&kh,    g_kh);
    cudaGetSymbolAddress((void**)&vT,    g_vT);
    cudaGetSymbolAddress((void**)&attnh, g_attnh);

    cudaFuncSetAttribute(f16_gemm<0>,
                         cudaFuncAttributeMaxDynamicSharedMemorySize, GSM_B);
    cudaFuncSetAttribute(f16_gemm<1>,
                         cudaFuncAttributeMaxDynamicSharedMemorySize, GSM_B);
    cudaFuncSetAttribute(flash_rpe_f16,
                         cudaFuncAttributeMaxDynamicSharedMemorySize, FSM_B);

    // 0) fp32 -> fp16 converts
    cvt_half_kernel<<<BT * Dv / 1024, 256>>>(x, xh, BT * Dv);
    cvt_half_kernel<<<3 * Dv * Dv / 1024, 256>>>(qkv_w, wh, 3 * Dv * Dv);
    cvt_half_kernel<<<Dv * Dv / 1024, 256>>>(out_w, owh, Dv * Dv);

    // 1) RPE bias projection
    rpe_bias_kernel<<<512, 256>>>(rel_pos, rpe_w);

    // 2) QKV projection -> Q,K (half) + V transposed (half)
    {
        dim3 grid(3 * Dv / 128, BT / 128);
        f16_gemm<1><<<grid, 256, GSM_B>>>(xh, wh, qkv_b, nullptr,
                                          qh, kh, vT, BT, 3 * Dv, Dv);
    }

    // 3) flash attention with RPE (fp16 mma, register-resident P)
    {
        dim3 grid(Tv / QT, Hv, Bv);
        flash_rpe_f16<<<grid, 256, FSM_B>>>();
    }

    // 4) output projection -> fp32 out
    {
        dim3 grid(Dv / 128, BT / 128);
        f16_gemm<0><<<grid, 256, GSM_B>>>(attnh, owh, out_b, out,
                                          nullptr, nullptr, nullptr,
                                          BT, Dv, Dv);
    }
}

// round 9
// speedup vs baseline: 6.7738x; 1.1504x over previous
#include <cuda_runtime.h>
#include <cuda_fp16.h>
#include <math.h>
#include <stdint.h>

// Problem constants
#define Bv      2
#define Tv      2048
#define Dv      1024
#define Hv      16
#define HDv     64
#define MAXLEN  2048
#define NBIAS   (2 * MAXLEN - 1)   // 4095
#define BT      (Bv * Tv)          // 4096

// ---------------------------------------------------------------------------
// Scratch (device globals)
// ---------------------------------------------------------------------------
__device__ float  g_bias[4608];             // projected RPE bias (zero-padded)
__device__ __half g_xh[BT * Dv];            // x      (half)
__device__ __half g_wh[3 * Dv * Dv];        // qkv_w  (half)
__device__ __half g_owh[Dv * Dv];           // out_w  (half)
__device__ __half g_qh[BT * Dv];            // Q      [b*T+t][h*64+d]
__device__ __half g_kh[BT * Dv];            // K      [b*T+t][h*64+d]
__device__ __half g_vT[Bv * Hv * HDv * Tv]; // V^T  [(b*16+h)*64+d][token]
__device__ __half g_attnh[BT * Dv];         // attention output (half)

// ---------------------------------------------------------------------------
// PTX helpers (sm_103-base safe: cp.async + mma.sync only)
// ---------------------------------------------------------------------------
__device__ __forceinline__ uint32_t smem_u32(const void* p) {
    uint32_t a;
    asm("{ .reg .u64 t; cvta.to.shared.u64 t, %1; cvt.u32.u64 %0, t; }"
        : "=r"(a) : "l"(p));
    return a;
}
__device__ __forceinline__ void cp_async16(uint32_t saddr, const void* gptr) {
    asm volatile("cp.async.cg.shared.global [%0], [%1], 16;"
                 :: "r"(saddr), "l"(gptr) : "memory");
}
#define CP_COMMIT() asm volatile("cp.async.commit_group;" ::: "memory")
#define CP_WAIT(n)  asm volatile("cp.async.wait_group %0;" :: "n"(n) : "memory")

__device__ __forceinline__ void mma_f16(float c[4], const uint32_t a[4],
                                        const uint32_t b[2]) {
    asm volatile(
        "mma.sync.aligned.m16n8k16.row.col.f32.f16.f16.f32 "
        "{%0,%1,%2,%3}, {%4,%5,%6,%7}, {%8,%9}, {%0,%1,%2,%3};"
        : "+f"(c[0]), "+f"(c[1]), "+f"(c[2]), "+f"(c[3])
        : "r"(a[0]), "r"(a[1]), "r"(a[2]), "r"(a[3]),
          "r"(b[0]), "r"(b[1]));
}
__device__ __forceinline__ uint32_t pack_h2(float lo, float hi) {
    __half2 h = __floats2half2_rn(lo, hi);
    return *(uint32_t*)&h;
}

// ---------------------------------------------------------------------------
// Kernel 0: fp32 -> fp16 convert (n multiple of 1024)
// ---------------------------------------------------------------------------
__global__ void cvt_half_kernel(const float* __restrict__ in,
                                __half* __restrict__ out, int n) {
    int i = (blockIdx.x * blockDim.x + threadIdx.x) * 4;
    if (i < n) {
        float4 v = *(const float4*)(in + i);
        uint2 o;
        o.x = pack_h2(v.x, v.y);
        o.y = pack_h2(v.z, v.w);
        *(uint2*)&out[i] = o;
    }
}

// ---------------------------------------------------------------------------
// Kernel 1: bias_vec[j] = rel_pos[j,:] . rpe_w   (8 warps/block)
// ---------------------------------------------------------------------------
__global__ void rpe_bias_kernel(const float* __restrict__ rel_pos,
                                const float* __restrict__ rpe_w) {
    int wid = threadIdx.x >> 5, lane = threadIdx.x & 31;
    int j = blockIdx.x * 8 + wid;
    if (j >= NBIAS) return;
    float v = rel_pos[j * HDv + lane] * rpe_w[lane]
            + rel_pos[j * HDv + 32 + lane] * rpe_w[32 + lane];
    #pragma unroll
    for (int o = 16; o > 0; o >>= 1) v += __shfl_xor_sync(0xffffffffu, v, o);
    if (lane == 0) g_bias[j] = v;
}

// ---------------------------------------------------------------------------
// fp16 mma.sync GEMM: C = A(half) @ W(half)^T + bias(fp32)
// 128x128 CTA tile, BK=64 halfs (128B rows), 8 warps (2x4), 2-stage cp.async,
// 2 CTAs/SM. MODE 0: float out. MODE 1: Q,K half + V transposed scatter.
// ---------------------------------------------------------------------------
#define BKH    64                      // halfs per K-chunk
#define PAG    36                      // u32 pitch per row (32 data + 4 pad)
#define TILEU  (128 * PAG)             // 4608 u32 per operand tile
#define STGU   (2 * TILEU)             // 9216 u32 per stage
#define GSM_B  (2 * STGU * 4)          // 73728 bytes

template<int MODE>
__global__ void __launch_bounds__(256, 2)
f16_gemm(const __half* __restrict__ A, const __half* __restrict__ W,
         const float* __restrict__ bias, float* __restrict__ Cf,
         __half* __restrict__ qh, __half* __restrict__ kh,
         __half* __restrict__ vT, int M, int N, int K) {
    extern __shared__ uint32_t smu[];
    const uint32_t sbase = smem_u32(smu);
    const int tid  = threadIdx.x;
    const int wid  = tid >> 5;
    const int lane = tid & 31;
    const int q    = lane >> 2;
    const int t    = lane & 3;
    const int warp_m = wid >> 2;
    const int warp_n = wid & 3;
    const int bm = blockIdx.y * 128;
    const int bn = blockIdx.x * 128;
    const int nchunk = K / BKH;        // 16

    float acc[4][4][4];
    #pragma unroll
    for (int mi = 0; mi < 4; ++mi)
        #pragma unroll
        for (int ni = 0; ni < 4; ++ni)
            #pragma unroll
            for (int e = 0; e < 4; ++e) acc[mi][ni][e] = 0.f;

    auto load_chunk = [&](int c, int s) {
        const uint32_t ab = sbase + s * (STGU * 4);
        const uint32_t bb = ab + TILEU * 4;
        #pragma unroll
        for (int i = 0; i < 4; ++i) {
            int idx = tid + 256 * i;       // 0..1023
            int row = idx >> 3;            // 0..127
            int cc  = idx & 7;             // 16B chunk within 128B row
            uint32_t doff = (uint32_t)(row * PAG + cc * 4) * 4;
            cp_async16(ab + doff, A + (size_t)(bm + row) * K + c * BKH + cc * 8);
            cp_async16(bb + doff, W + (size_t)(bn + row) * K + c * BKH + cc * 8);
        }
    };

    load_chunk(0, 0); CP_COMMIT();
    load_chunk(1, 1); CP_COMMIT();

    for (int c = 0; c < nchunk; ++c) {
        const int s = c & 1;
        if (c + 1 < nchunk) { CP_WAIT(1); } else { CP_WAIT(0); }
        __syncthreads();

        const uint32_t* as = smu + s * STGU;
        const uint32_t* bs = as + TILEU;
        const int m_base = warp_m * 64;
        const int n_base = warp_n * 32;

        #pragma unroll
        for (int ks = 0; ks < 4; ++ks) {
            uint32_t af[4][4], bf[4][2];
            #pragma unroll
            for (int mi = 0; mi < 4; ++mi) {
                const uint32_t* p = as + (m_base + mi * 16 + q) * PAG + ks * 8 + t;
                af[mi][0] = p[0];
                af[mi][1] = p[8 * PAG];
                af[mi][2] = p[4];
                af[mi][3] = p[8 * PAG + 4];
            }
            #pragma unroll
            for (int ni = 0; ni < 4; ++ni) {
                const uint32_t* p = bs + (n_base + ni * 8 + q) * PAG + ks * 8 + t;
                bf[ni][0] = p[0];
                bf[ni][1] = p[4];
            }
            #pragma unroll
            for (int mi = 0; mi < 4; ++mi)
                #pragma unroll
                for (int ni = 0; ni < 4; ++ni)
                    mma_f16(acc[mi][ni], af[mi], bf[ni]);
        }

        __syncthreads();
        if (c + 2 < nchunk) { load_chunk(c + 2, s); CP_COMMIT(); }
    }

    #pragma unroll
    for (int mi = 0; mi < 4; ++mi) {
        const int row0 = bm + warp_m * 64 + mi * 16 + q;
        #pragma unroll
        for (int ni = 0; ni < 4; ++ni) {
            const int col = bn + warp_n * 32 + ni * 8 + 2 * t;
            const float b0 = bias[col], b1 = bias[col + 1];
            float o00 = acc[mi][ni][0] + b0, o01 = acc[mi][ni][1] + b1;
            float o10 = acc[mi][ni][2] + b0, o11 = acc[mi][ni][3] + b1;
            if (MODE == 0) {
                *(float2*)&Cf[(size_t)row0 * N + col] = make_float2(o00, o01);
                *(float2*)&Cf[(size_t)(row0 + 8) * N + col] = make_float2(o10, o11);
            } else {
                if (bn < 2048) {
                    __half* dst = (bn < 1024) ? qh : kh;
                    int coln = (bn < 1024) ? col : col - 1024;
                    *(uint32_t*)&dst[(size_t)row0 * 1024 + coln] = pack_h2(o00, o01);
                    *(uint32_t*)&dst[(size_t)(row0 + 8) * 1024 + coln] = pack_h2(o10, o11);
                } else {
                    int hd = col - 2048;
                    int h = hd >> 6, d = hd & 63;
                    int bb = row0 >> 11, token = row0 & 2047;
                    __half* base = vT + ((size_t)((bb * 16 + h) * 64 + d)) * 2048 + token;
                    base[0]        = __float2half_rn(o00);
                    base[2048]     = __float2half_rn(o01);
                    base[8]        = __float2half_rn(o10);
                    base[2048 + 8] = __float2half_rn(o11);
                }
            }
        }
    }
}

// ---------------------------------------------------------------------------
// Kernel 3: flash attention with RPE, fp16 mma.sync.
// CTA: 128 q-rows x one (b,h); 8 warps, warp w owns rows [16w,16w+16).
// KT=64 keys/iter double-buffered (32 iterations). P register-resident.
// ---------------------------------------------------------------------------
#define QT    128
#define KT    64
#define QPA   36                         // u32 pitch, Q/K rows (32 data + 4)
#define VPA   36                         // u32 pitch, V^T rows (KT=64 halfs)
#define OFF_Q   0                        // 128*36 = 4608 u32
#define OFF_K   (OFF_Q + QT * QPA)       // + 2*64*36 = 4608
#define OFF_V   (OFF_K + 2 * KT * QPA)   // + 2*64*36 = 4608
#define OFF_BW  (OFF_V + 2 * HDv * VPA)  // + 2*192
#define FSMU    (OFF_BW + 2 * 192)       // 14208 u32
#define FSM_B   (FSMU * 4)               // 56832 bytes

__global__ void __launch_bounds__(256, 2)
flash_rpe_f16() {
    extern __shared__ uint32_t smu[];
    const uint32_t sb = smem_u32(smu);
    float* smf = (float*)smu;
    const int b = blockIdx.z, h = blockIdx.y;
    const int qbase = blockIdx.x * QT;
    const int tid = threadIdx.x, wid = tid >> 5, lane = tid & 31;
    const int q = lane >> 2, t = lane & 3;
    const int mb = wid * 16;
    const float scale = 0.125f;

    // ---- Q tile via cp.async (in group 0 with kv0) ----
    #pragma unroll
    for (int i = 0; i < 4; ++i) {
        int idx = tid + 256 * i;          // 0..1023
        int row = idx >> 3;               // 0..127
        int c8  = idx & 7;
        cp_async16(sb + (uint32_t)(OFF_Q + row * QPA + c8 * 4) * 4,
                   g_qh + (size_t)(b * Tv + qbase + row) * 1024 + h * 64 + c8 * 8);
    }

    auto load_kv = [&](int kt, int s) {
        const int kbase = kt * KT;
        const uint32_t kb = sb + (uint32_t)(OFF_K + s * KT * QPA) * 4;
        const uint32_t vb = sb + (uint32_t)(OFF_V + s * HDv * VPA) * 4;
        #pragma unroll
        for (int i = 0; i < 2; ++i) {
            int idx = tid + 256 * i;       // 0..511
            int row = idx >> 3;            // 0..63
            int c8  = idx & 7;
            // K: token rows, 64 halfs each
            cp_async16(kb + (uint32_t)(row * QPA + c8 * 4) * 4,
                       g_kh + (size_t)(b * Tv + kbase + row) * 1024 + h * 64 + c8 * 8);
            // V^T: d rows, KT=64 token halfs each
            cp_async16(vb + (uint32_t)(row * VPA + c8 * 4) * 4,
                       g_vT + (size_t)((b * 16 + h) * 64 + row) * 2048 + kbase + c8 * 8);
        }
        if (tid < 48) {
            int base = kbase - qbase + 1920;   // 16B aligned
            cp_async16(sb + (uint32_t)(OFF_BW + s * 192 + tid * 4) * 4,
                       &g_bias[base + tid * 4]);
        }
    };

    load_kv(0, 0); CP_COMMIT();
    load_kv(1, 1); CP_COMMIT();

    float m0 = -INFINITY, m1 = -INFINITY, l0 = 0.f, l1 = 0.f;
    float ao[8][4];
    #pragma unroll
    for (int ni = 0; ni < 8; ++ni)
        #pragma unroll
        for (int e = 0; e < 4; ++e) ao[ni][e] = 0.f;

    const int NIT = Tv / KT;   // 32
    for (int kt = 0; kt < NIT; ++kt) {
        const int s = kt & 1;
        if (kt < NIT - 1) { CP_WAIT(1); } else { CP_WAIT(0); }
        __syncthreads();

        const uint32_t* Ksu = smu + OFF_K + s * KT * QPA;
        const uint32_t* Vsu = smu + OFF_V + s * HDv * VPA;
        const float* bw = smf + OFF_BW + s * 192;

        // ---- S = Q K^T (warp: 16 rows x 64 cols) ----
        float as_[8][4];
        #pragma unroll
        for (int ni = 0; ni < 8; ++ni)
            #pragma unroll
            for (int e = 0; e < 4; ++e) as_[ni][e] = 0.f;

        #pragma unroll
        for (int ks = 0; ks < 4; ++ks) {
            uint32_t af[4];
            const uint32_t* pa = smu + OFF_Q + (mb + q) * QPA + ks * 8 + t;
            af[0] = pa[0];
            af[1] = pa[8 * QPA];
            af[2] = pa[4];
            af[3] = pa[8 * QPA + 4];
            #pragma unroll
            for (int ni = 0; ni < 8; ++ni) {
                uint32_t bf[2];
                const uint32_t* pb = Ksu + (ni * 8 + q) * QPA + ks * 8 + t;
                bf[0] = pb[0];
                bf[1] = pb[4];
                mma_f16(as_[ni], af, bf);
            }
        }

        // ---- scale + bias; row max ----
        float mx0 = -INFINITY, mx1 = -INFINITY;
        #pragma unroll
        for (int ni = 0; ni < 8; ++ni) {
            const int i0 = ni * 8 + 2 * t - mb - q + 127;
            as_[ni][0] = fmaf(as_[ni][0], scale, bw[i0]);
            as_[ni][1] = fmaf(as_[ni][1], scale, bw[i0 + 1]);
            as_[ni][2] = fmaf(as_[ni][2], scale, bw[i0 - 8]);
            as_[ni][3] = fmaf(as_[ni][3], scale, bw[i0 - 7]);
            mx0 = fmaxf(mx0, fmaxf(as_[ni][0], as_[ni][1]));
            mx1 = fmaxf(mx1, fmaxf(as_[ni][2], as_[ni][3]));
        }
        #pragma unroll
        for (int off = 1; off <= 2; off <<= 1) {
            mx0 = fmaxf(mx0, __shfl_xor_sync(0xffffffffu, mx0, off));
            mx1 = fmaxf(mx1, __shfl_xor_sync(0xffffffffu, mx1, off));
        }
        const float mn0 = fmaxf(m0, mx0), mn1 = fmaxf(m1, mx1);
        const float c0 = __expf(m0 - mn0), c1 = __expf(m1 - mn1);
        m0 = mn0; m1 = mn1;

        // ---- exp; P packed to half2 in registers; row sums ----
        float rs0 = 0.f, rs1 = 0.f;
        uint32_t pf[8][2];
        #pragma unroll
        for (int ni = 0; ni < 8; ++ni) {
            float p0 = __expf(as_[ni][0] - mn0);
            float p1 = __expf(as_[ni][1] - mn0);
            float p2 = __expf(as_[ni][2] - mn1);
            float p3 = __expf(as_[ni][3] - mn1);
            rs0 += p0 + p1; rs1 += p2 + p3;
            pf[ni][0] = pack_h2(p0, p1);   // row q
            pf[ni][1] = pack_h2(p2, p3);   // row q+8
        }
        #pragma unroll
        for (int off = 1; off <= 2; off <<= 1) {
            rs0 += __shfl_xor_sync(0xffffffffu, rs0, off);
            rs1 += __shfl_xor_sync(0xffffffffu, rs1, off);
        }
        l0 = l0 * c0 + rs0;
        l1 = l1 * c1 + rs1;
        #pragma unroll
        for (int ni = 0; ni < 8; ++ni) {
            ao[ni][0] *= c0; ao[ni][1] *= c0;
            ao[ni][2] *= c1; ao[ni][3] *= c1;
        }

        // ---- O += P @ V : A-frags thread-local, B from V^T ----
        #pragma unroll
        for (int ks = 0; ks < 4; ++ks) {
            uint32_t af[4];
            af[0] = pf[2 * ks][0];
            af[1] = pf[2 * ks][1];
            af[2] = pf[2 * ks + 1][0];
            af[3] = pf[2 * ks + 1][1];
            #pragma unroll
            for (int ni = 0; ni < 8; ++ni) {
                uint32_t bf[2];
                const uint32_t* pb = Vsu + (ni * 8 + q) * VPA + ks * 8 + t;
                bf[0] = pb[0];
                bf[1] = pb[4];
                mma_f16(ao[ni], af, bf);
            }
        }

        __syncthreads();   // all warps done with stage s before refill
        if (kt + 2 < NIT) { load_kv(kt + 2, s); CP_COMMIT(); }
    }

    // ---- normalize, write half attn ----
    const float inv0 = 1.f / l0, inv1 = 1.f / l1;
    const int r0 = qbase + mb + q;
    #pragma unroll
    for (int ni = 0; ni < 8; ++ni) {
        const int col = h * HDv + ni * 8 + 2 * t;
        *(uint32_t*)&g_attnh[(size_t)(b * Tv + r0) * Dv + col]
            = pack_h2(ao[ni][0] * inv0, ao[ni][1] * inv0);
        *(uint32_t*)&g_attnh[(size_t)(b * Tv + r0 + 8) * Dv + col]
            = pack_h2(ao[ni][2] * inv1, ao[ni][3] * inv1);
    }
}

// ---------------------------------------------------------------------------
// Launcher
// ---------------------------------------------------------------------------
extern "C" void kernel_launch(void* const* d_in, const int* in_sizes, int n_in,
                              void* d_out, int out_size) {
    const float* x       = (const float*)d_in[0];
    const float* qkv_w   = (const float*)d_in[1];
    const float* qkv_b   = (const float*)d_in[2];
    const float* out_w   = (const float*)d_in[3];
    const float* out_b   = (const float*)d_in[4];
    const float* rel_pos = (const float*)d_in[5];
    const float* rpe_w   = (const float*)d_in[6];
    float* out = (float*)d_out;

    __half *xh, *wh, *owh, *qh, *kh, *vT, *attnh;
    cudaGetSymbolAddress((void**)&xh,    g_xh);
    cudaGetSymbolAddress((void**)&wh,    g_wh);
    cudaGetSymbolAddress((void**)&owh,   g_owh);
    cudaGetSymbolAddress((void**)&qh,    g_qh);
    cudaGetSymbolAddress((void**)&kh,    g_kh);
    cudaGetSymbolAddress((void**)&vT,    g_vT);
    cudaGetSymbolAddress((void**)&attnh, g_attnh);

    cudaFuncSetAttribute(f16_gemm<0>,
                         cudaFuncAttributeMaxDynamicSharedMemorySize, GSM_B);
    cudaFuncSetAttribute(f16_gemm<1>,
                         cudaFuncAttributeMaxDynamicSharedMemorySize, GSM_B);
    cudaFuncSetAttribute(flash_rpe_f16,
                         cudaFuncAttributeMaxDynamicSharedMemorySize, FSM_B);

    // 0) fp32 -> fp16 converts
    cvt_half_kernel<<<BT * Dv / 1024, 256>>>(x, xh, BT * Dv);
    cvt_half_kernel<<<3 * Dv * Dv / 1024, 256>>>(qkv_w, wh, 3 * Dv * Dv);
    cvt_half_kernel<<<Dv * Dv / 1024, 256>>>(out_w, owh, Dv * Dv);

    // 1) RPE bias projection
    rpe_bias_kernel<<<512, 256>>>(rel_pos, rpe_w);

    // 2) QKV projection -> Q,K (half) + V transposed (half)
    {
        dim3 grid(3 * Dv / 128, BT / 128);
        f16_gemm<1><<<grid, 256, GSM_B>>>(xh, wh, qkv_b, nullptr,
                                          qh, kh, vT, BT, 3 * Dv, Dv);
    }

    // 3) flash attention with RPE (fp16 mma, register-resident P, KT=64)
    {
        dim3 grid(Tv / QT, Hv, Bv);
        flash_rpe_f16<<<grid, 256, FSM_B>>>();
    }

    // 4) output projection -> fp32 out
    {
        dim3 grid(Dv / 128, BT / 128);
        f16_gemm<0><<<grid, 256, GSM_B>>>(attnh, owh, out_b, out,
                                          nullptr, nullptr, nullptr,
                                          BT, Dv, Dv);
    }
}

// round 10
// speedup vs baseline: 7.3166x; 1.0801x over previous
#include <cuda_runtime.h>
#include <cuda_fp16.h>
#include <math.h>
#include <stdint.h>

// Problem constants
#define Bv      2
#define Tv      2048
#define Dv      1024
#define Hv      16
#define HDv     64
#define MAXLEN  2048
#define NBIAS   (2 * MAXLEN - 1)   // 4095
#define BT      (Bv * Tv)          // 4096

// ---------------------------------------------------------------------------
// Scratch (device globals)
// ---------------------------------------------------------------------------
__device__ float  g_bias[4608];             // projected RPE bias (zero-padded)
__device__ __half g_xh[BT * Dv];            // x      (half)
__device__ __half g_wh[3 * Dv * Dv];        // qkv_w  (half)
__device__ __half g_owh[Dv * Dv];           // out_w  (half)
__device__ __half g_qh[BT * Dv];            // Q      [b*T+t][h*64+d]
__device__ __half g_kh[BT * Dv];            // K      [b*T+t][h*64+d]
__device__ __half g_vT[Bv * Hv * HDv * Tv]; // V^T  [(b*16+h)*64+d][token]
__device__ __half g_attnh[BT * Dv];         // attention output (half)

// ---------------------------------------------------------------------------
// PTX helpers (sm_103-base safe: cp.async + mma.sync + ldmatrix)
// ---------------------------------------------------------------------------
__device__ __forceinline__ uint32_t smem_u32(const void* p) {
    uint32_t a;
    asm("{ .reg .u64 t; cvta.to.shared.u64 t, %1; cvt.u32.u64 %0, t; }"
        : "=r"(a) : "l"(p));
    return a;
}
__device__ __forceinline__ void cp_async16(uint32_t saddr, const void* gptr) {
    asm volatile("cp.async.cg.shared.global [%0], [%1], 16;"
                 :: "r"(saddr), "l"(gptr) : "memory");
}
#define CP_COMMIT() asm volatile("cp.async.commit_group;" ::: "memory")
#define CP_WAIT(n)  asm volatile("cp.async.wait_group %0;" :: "n"(n) : "memory")

__device__ __forceinline__ void ldsm_x4(uint32_t r[4], uint32_t addr) {
    asm volatile("ldmatrix.sync.aligned.m8n8.x4.shared.b16 {%0,%1,%2,%3}, [%4];"
                 : "=r"(r[0]), "=r"(r[1]), "=r"(r[2]), "=r"(r[3])
                 : "r"(addr));
}
__device__ __forceinline__ void mma_f16(float c[4], const uint32_t a[4],
                                        const uint32_t b[2]) {
    asm volatile(
        "mma.sync.aligned.m16n8k16.row.col.f32.f16.f16.f32 "
        "{%0,%1,%2,%3}, {%4,%5,%6,%7}, {%8,%9}, {%0,%1,%2,%3};"
        : "+f"(c[0]), "+f"(c[1]), "+f"(c[2]), "+f"(c[3])
        : "r"(a[0]), "r"(a[1]), "r"(a[2]), "r"(a[3]),
          "r"(b[0]), "r"(b[1]));
}
__device__ __forceinline__ uint32_t pack_h2(float lo, float hi) {
    __half2 h = __floats2half2_rn(lo, hi);
    return *(uint32_t*)&h;
}

// ---------------------------------------------------------------------------
// Kernel 0: fused fp32 -> fp16 convert of x, qkv_w, out_w
// units of 4 elems: x 1048576 | w 786432 | ow 262144  (total 2097152)
// ---------------------------------------------------------------------------
__global__ void cvt_all_kernel(const float* __restrict__ x,
                               const float* __restrict__ w,
                               const float* __restrict__ ow,
                               __half* __restrict__ xh,
                               __half* __restrict__ wh,
                               __half* __restrict__ owh) {
    int u = blockIdx.x * blockDim.x + threadIdx.x;
    const float* src;
    __half* dst;
    int idx;
    if (u < 1048576)       { src = x;  dst = xh;  idx = u; }
    else if (u < 1835008)  { src = w;  dst = wh;  idx = u - 1048576; }
    else                   { src = ow; dst = owh; idx = u - 1835008; }
    int i = idx * 4;
    float4 v = *(const float4*)(src + i);
    uint2 o;
    o.x = pack_h2(v.x, v.y);
    o.y = pack_h2(v.z, v.w);
    *(uint2*)&dst[i] = o;
}

// ---------------------------------------------------------------------------
// Kernel 1: bias_vec[j] = rel_pos[j,:] . rpe_w   (8 warps/block)
// ---------------------------------------------------------------------------
__global__ void rpe_bias_kernel(const float* __restrict__ rel_pos,
                                const float* __restrict__ rpe_w) {
    int wid = threadIdx.x >> 5, lane = threadIdx.x & 31;
    int j = blockIdx.x * 8 + wid;
    if (j >= NBIAS) return;
    float v = rel_pos[j * HDv + lane] * rpe_w[lane]
            + rel_pos[j * HDv + 32 + lane] * rpe_w[32 + lane];
    #pragma unroll
    for (int o = 16; o > 0; o >>= 1) v += __shfl_xor_sync(0xffffffffu, v, o);
    if (lane == 0) g_bias[j] = v;
}

// ---------------------------------------------------------------------------
// fp16 mma.sync GEMM with ldmatrix fragment feed.
// 128x128 CTA tile, BK=64 halfs, 8 warps (2x4), 2-stage cp.async, 2 CTAs/SM.
// ---------------------------------------------------------------------------
#define BKH    64                      // halfs per K-chunk
#define PAG    36                      // u32 pitch per row (32 data + 4 pad)
#define TILEU  (128 * PAG)             // u32 per operand tile
#define STGU   (2 * TILEU)             // u32 per stage
#define GSM_B  (2 * STGU * 4)          // 73728 bytes

template<int MODE>
__global__ void __launch_bounds__(256, 2)
f16_gemm(const __half* __restrict__ A, const __half* __restrict__ W,
         const float* __restrict__ bias, float* __restrict__ Cf,
         __half* __restrict__ qh, __half* __restrict__ kh,
         __half* __restrict__ vT, int M, int N, int K) {
    extern __shared__ uint32_t smu[];
    const uint32_t sbase = smem_u32(smu);
    const int tid  = threadIdx.x;
    const int wid  = tid >> 5;
    const int lane = tid & 31;
    const int q    = lane >> 2;
    const int t    = lane & 3;
    const int warp_m = wid >> 2;
    const int warp_n = wid & 3;
    const int bm = blockIdx.y * 128;
    const int bn = blockIdx.x * 128;
    const int nchunk = K / BKH;        // 16

    // ldmatrix per-thread addressing
    const int lr   = lane & 15;                        // A row within 16
    const int lc   = (lane >> 4) * 4;                  // A 16B chunk (u32)
    const int brow = (lane & 7) | ((lane >> 4) << 3);  // B row within 16
    const int bsub = ((lane >> 3) & 1) * 4;            // B 16B chunk (u32)

    float acc[4][4][4];
    #pragma unroll
    for (int mi = 0; mi < 4; ++mi)
        #pragma unroll
        for (int ni = 0; ni < 4; ++ni)
            #pragma unroll
            for (int e = 0; e < 4; ++e) acc[mi][ni][e] = 0.f;

    auto load_chunk = [&](int c, int s) {
        const uint32_t ab = sbase + s * (STGU * 4);
        const uint32_t bb = ab + TILEU * 4;
        #pragma unroll
        for (int i = 0; i < 4; ++i) {
            int idx = tid + 256 * i;       // 0..1023
            int row = idx >> 3;            // 0..127
            int cc  = idx & 7;
            uint32_t doff = (uint32_t)(row * PAG + cc * 4) * 4;
            cp_async16(ab + doff, A + (size_t)(bm + row) * K + c * BKH + cc * 8);
            cp_async16(bb + doff, W + (size_t)(bn + row) * K + c * BKH + cc * 8);
        }
    };

    load_chunk(0, 0); CP_COMMIT();
    load_chunk(1, 1); CP_COMMIT();

    // invariant ldmatrix base addrs (u32 units, stage 0)
    uint32_t a_base[4], b_base[2];
    #pragma unroll
    for (int mi = 0; mi < 4; ++mi)
        a_base[mi] = sbase + (uint32_t)((warp_m * 64 + mi * 16 + lr) * PAG + lc) * 4;
    #pragma unroll
    for (int p = 0; p < 2; ++p)
        b_base[p] = sbase + (uint32_t)(TILEU + (warp_n * 32 + p * 16 + brow) * PAG + bsub) * 4;

    for (int c = 0; c < nchunk; ++c) {
        const int s = c & 1;
        if (c + 1 < nchunk) { CP_WAIT(1); } else { CP_WAIT(0); }
        __syncthreads();
        const uint32_t soff = (uint32_t)(s * STGU * 4);

        #pragma unroll
        for (int ks = 0; ks < 4; ++ks) {
            const uint32_t ko = soff + ks * 32;
            uint32_t af[4][4], bq[2][4];
            #pragma unroll
            for (int mi = 0; mi < 4; ++mi) ldsm_x4(af[mi], a_base[mi] + ko);
            #pragma unroll
            for (int p = 0; p < 2; ++p)   ldsm_x4(bq[p], b_base[p] + ko);
            #pragma unroll
            for (int mi = 0; mi < 4; ++mi)
                #pragma unroll
                for (int ni = 0; ni < 4; ++ni)
                    mma_f16(acc[mi][ni], af[mi], &bq[ni >> 1][(ni & 1) * 2]);
        }

        __syncthreads();
        if (c + 2 < nchunk) { load_chunk(c + 2, s); CP_COMMIT(); }
    }

    #pragma unroll
    for (int mi = 0; mi < 4; ++mi) {
        const int row0 = bm + warp_m * 64 + mi * 16 + q;
        #pragma unroll
        for (int ni = 0; ni < 4; ++ni) {
            const int col = bn + warp_n * 32 + ni * 8 + 2 * t;
            const float b0 = bias[col], b1 = bias[col + 1];
            float o00 = acc[mi][ni][0] + b0, o01 = acc[mi][ni][1] + b1;
            float o10 = acc[mi][ni][2] + b0, o11 = acc[mi][ni][3] + b1;
            if (MODE == 0) {
                *(float2*)&Cf[(size_t)row0 * N + col] = make_float2(o00, o01);
                *(float2*)&Cf[(size_t)(row0 + 8) * N + col] = make_float2(o10, o11);
            } else {
                if (bn < 2048) {
                    __half* dst = (bn < 1024) ? qh : kh;
                    int coln = (bn < 1024) ? col : col - 1024;
                    *(uint32_t*)&dst[(size_t)row0 * 1024 + coln] = pack_h2(o00, o01);
                    *(uint32_t*)&dst[(size_t)(row0 + 8) * 1024 + coln] = pack_h2(o10, o11);
                } else {
                    int hd = col - 2048;
                    int h = hd >> 6, d = hd & 63;
                    int bb = row0 >> 11, token = row0 & 2047;
                    __half* base = vT + ((size_t)((bb * 16 + h) * 64 + d)) * 2048 + token;
                    base[0]        = __float2half_rn(o00);
                    base[2048]     = __float2half_rn(o01);
                    base[8]        = __float2half_rn(o10);
                    base[2048 + 8] = __float2half_rn(o11);
                }
            }
        }
    }
}

// ---------------------------------------------------------------------------
// Kernel 3: flash attention with RPE, fp16 mma.sync + ldmatrix.
// CTA: 128 q-rows x one (b,h); 8 warps; KT=64 double-buffered; P in registers.
// ---------------------------------------------------------------------------
#define QT    128
#define KT    64
#define QPA   36
#define VPA   36
#define OFF_Q   0
#define OFF_K   (OFF_Q + QT * QPA)
#define OFF_V   (OFF_K + 2 * KT * QPA)
#define OFF_BW  (OFF_V + 2 * HDv * VPA)
#define FSMU    (OFF_BW + 2 * 192)
#define FSM_B   (FSMU * 4)               // 56832 bytes

__global__ void __launch_bounds__(256, 2)
flash_rpe_f16() {
    extern __shared__ uint32_t smu[];
    const uint32_t sb = smem_u32(smu);
    float* smf = (float*)smu;
    const int b = blockIdx.z, h = blockIdx.y;
    const int qbase = blockIdx.x * QT;
    const int tid = threadIdx.x, wid = tid >> 5, lane = tid & 31;
    const int q = lane >> 2, t = lane & 3;
    const int mb = wid * 16;
    const float scale = 0.125f;

    const int lr   = lane & 15;
    const int lc   = (lane >> 4) * 4;
    const int brow = (lane & 7) | ((lane >> 4) << 3);
    const int bsub = ((lane >> 3) & 1) * 4;

    // ---- Q tile via cp.async (in group 0 with kv0) ----
    #pragma unroll
    for (int i = 0; i < 4; ++i) {
        int idx = tid + 256 * i;
        int row = idx >> 3;
        int c8  = idx & 7;
        cp_async16(sb + (uint32_t)(OFF_Q + row * QPA + c8 * 4) * 4,
                   g_qh + (size_t)(b * Tv + qbase + row) * 1024 + h * 64 + c8 * 8);
    }

    auto load_kv = [&](int kt, int s) {
        const int kbase = kt * KT;
        const uint32_t kb = sb + (uint32_t)(OFF_K + s * KT * QPA) * 4;
        const uint32_t vb = sb + (uint32_t)(OFF_V + s * HDv * VPA) * 4;
        #pragma unroll
        for (int i = 0; i < 2; ++i) {
            int idx = tid + 256 * i;
            int row = idx >> 3;
            int c8  = idx & 7;
            cp_async16(kb + (uint32_t)(row * QPA + c8 * 4) * 4,
                       g_kh + (size_t)(b * Tv + kbase + row) * 1024 + h * 64 + c8 * 8);
            cp_async16(vb + (uint32_t)(row * VPA + c8 * 4) * 4,
                       g_vT + (size_t)((b * 16 + h) * 64 + row) * 2048 + kbase + c8 * 8);
        }
        if (tid < 48) {
            int base = kbase - qbase + 1920;
            cp_async16(sb + (uint32_t)(OFF_BW + s * 192 + tid * 4) * 4,
                       &g_bias[base + tid * 4]);
        }
    };

    load_kv(0, 0); CP_COMMIT();
    load_kv(1, 1); CP_COMMIT();

    // invariant ldmatrix bases
    const uint32_t q_base = sb + (uint32_t)(OFF_Q + (mb + lr) * QPA + lc) * 4;
    uint32_t k_base[4], v_base[4];
    #pragma unroll
    for (int p = 0; p < 4; ++p) {
        k_base[p] = sb + (uint32_t)(OFF_K + (p * 16 + brow) * QPA + bsub) * 4;
        v_base[p] = sb + (uint32_t)(OFF_V + (p * 16 + brow) * VPA + bsub) * 4;
    }

    float m0 = -INFINITY, m1 = -INFINITY, l0 = 0.f, l1 = 0.f;
    float ao[8][4];
    #pragma unroll
    for (int ni = 0; ni < 8; ++ni)
        #pragma unroll
        for (int e = 0; e < 4; ++e) ao[ni][e] = 0.f;

    const int NIT = Tv / KT;   // 32
    for (int kt = 0; kt < NIT; ++kt) {
        const int s = kt & 1;
        if (kt < NIT - 1) { CP_WAIT(1); } else { CP_WAIT(0); }
        __syncthreads();

        const uint32_t ksoff = (uint32_t)(s * KT * QPA * 4);
        const uint32_t vsoff = (uint32_t)(s * HDv * VPA * 4);
        const float* bw = smf + OFF_BW + s * 192;

        // ---- S = Q K^T (warp: 16 rows x 64 cols) ----
        float as_[8][4];
        #pragma unroll
        for (int ni = 0; ni < 8; ++ni)
            #pragma unroll
            for (int e = 0; e < 4; ++e) as_[ni][e] = 0.f;

        #pragma unroll
        for (int ks = 0; ks < 4; ++ks) {
            const uint32_t ko = ks * 32;
            uint32_t af[4];
            ldsm_x4(af, q_base + ko);
            #pragma unroll
            for (int p = 0; p < 4; ++p) {
                uint32_t kq[4];
                ldsm_x4(kq, k_base[p] + ksoff + ko);
                mma_f16(as_[2 * p],     af, &kq[0]);
                mma_f16(as_[2 * p + 1], af, &kq[2]);
            }
        }

        // ---- scale + bias; row max ----
        float mx0 = -INFINITY, mx1 = -INFINITY;
        #pragma unroll
        for (int ni = 0; ni < 8; ++ni) {
            const int i0 = ni * 8 + 2 * t - mb - q + 127;
            as_[ni][0] = fmaf(as_[ni][0], scale, bw[i0]);
            as_[ni][1] = fmaf(as_[ni][1], scale, bw[i0 + 1]);
            as_[ni][2] = fmaf(as_[ni][2], scale, bw[i0 - 8]);
            as_[ni][3] = fmaf(as_[ni][3], scale, bw[i0 - 7]);
            mx0 = fmaxf(mx0, fmaxf(as_[ni][0], as_[ni][1]));
            mx1 = fmaxf(mx1, fmaxf(as_[ni][2], as_[ni][3]));
        }
        #pragma unroll
        for (int off = 1; off <= 2; off <<= 1) {
            mx0 = fmaxf(mx0, __shfl_xor_sync(0xffffffffu, mx0, off));
            mx1 = fmaxf(mx1, __shfl_xor_sync(0xffffffffu, mx1, off));
        }
        const float mn0 = fmaxf(m0, mx0), mn1 = fmaxf(m1, mx1);
        const float c0 = __expf(m0 - mn0), c1 = __expf(m1 - mn1);
        m0 = mn0; m1 = mn1;

        // ---- exp; P packed to half2 in registers; row sums ----
        float rs0 = 0.f, rs1 = 0.f;
        uint32_t pf[8][2];
        #pragma unroll
        for (int ni = 0; ni < 8; ++ni) {
            float p0 = __expf(as_[ni][0] - mn0);
            float p1 = __expf(as_[ni][1] - mn0);
            float p2 = __expf(as_[ni][2] - mn1);
            float p3 = __expf(as_[ni][3] - mn1);
            rs0 += p0 + p1; rs1 += p2 + p3;
            pf[ni][0] = pack_h2(p0, p1);
            pf[ni][1] = pack_h2(p2, p3);
        }
        #pragma unroll
        for (int off = 1; off <= 2; off <<= 1) {
            rs0 += __shfl_xor_sync(0xffffffffu, rs0, off);
            rs1 += __shfl_xor_sync(0xffffffffu, rs1, off);
        }
        l0 = l0 * c0 + rs0;
        l1 = l1 * c1 + rs1;
        #pragma unroll
        for (int ni = 0; ni < 8; ++ni) {
            ao[ni][0] *= c0; ao[ni][1] *= c0;
            ao[ni][2] *= c1; ao[ni][3] *= c1;
        }

        // ---- O += P @ V : A-frags thread-local, B via ldmatrix ----
        #pragma unroll
        for (int ks = 0; ks < 4; ++ks) {
            const uint32_t ko = ks * 32;
            uint32_t af[4];
            af[0] = pf[2 * ks][0];
            af[1] = pf[2 * ks][1];
            af[2] = pf[2 * ks + 1][0];
            af[3] = pf[2 * ks + 1][1];
            #pragma unroll
            for (int p = 0; p < 4; ++p) {
                uint32_t vq[4];
                ldsm_x4(vq, v_base[p] + vsoff + ko);
                mma_f16(ao[2 * p],     af, &vq[0]);
                mma_f16(ao[2 * p + 1], af, &vq[2]);
            }
        }

        __syncthreads();
        if (kt + 2 < NIT) { load_kv(kt + 2, s); CP_COMMIT(); }
    }

    // ---- normalize, write half attn ----
    const float inv0 = 1.f / l0, inv1 = 1.f / l1;
    const int r0 = qbase + mb + q;
    #pragma unroll
    for (int ni = 0; ni < 8; ++ni) {
        const int col = h * HDv + ni * 8 + 2 * t;
        *(uint32_t*)&g_attnh[(size_t)(b * Tv + r0) * Dv + col]
            = pack_h2(ao[ni][0] * inv0, ao[ni][1] * inv0);
        *(uint32_t*)&g_attnh[(size_t)(b * Tv + r0 + 8) * Dv + col]
            = pack_h2(ao[ni][2] * inv1, ao[ni][3] * inv1);
    }
}

// ---------------------------------------------------------------------------
// Launcher
// ---------------------------------------------------------------------------
extern "C" void kernel_launch(void* const* d_in, const int* in_sizes, int n_in,
                              void* d_out, int out_size) {
    const float* x       = (const float*)d_in[0];
    const float* qkv_w   = (const float*)d_in[1];
    const float* qkv_b   = (const float*)d_in[2];
    const float* out_w   = (const float*)d_in[3];
    const float* out_b   = (const float*)d_in[4];
    const float* rel_pos = (const float*)d_in[5];
    const float* rpe_w   = (const float*)d_in[6];
    float* out = (float*)d_out;

    __half *xh, *wh, *owh, *qh, *kh, *vT, *attnh;
    cudaGetSymbolAddress((void**)&xh,    g_xh);
    cudaGetSymbolAddress((void**)&wh,    g_wh);
    cudaGetSymbolAddress((void**)&owh,   g_owh);
    cudaGetSymbolAddress((void**)&qh,    g_qh);
    cudaGetSymbolAddress((void**)&kh,    g_kh);
    cudaGetSymbolAddress((void**)&vT,    g_vT);
    cudaGetSymbolAddress((void**)&attnh, g_attnh);

    cudaFuncSetAttribute(f16_gemm<0>,
                         cudaFuncAttributeMaxDynamicSharedMemorySize, GSM_B);
    cudaFuncSetAttribute(f16_gemm<1>,
                         cudaFuncAttributeMaxDynamicSharedMemorySize, GSM_B);
    cudaFuncSetAttribute(flash_rpe_f16,
                         cudaFuncAttributeMaxDynamicSharedMemorySize, FSM_B);

    // 0) fused fp32 -> fp16 converts (x, qkv_w, out_w)
    cvt_all_kernel<<<8192, 256>>>(x, qkv_w, out_w, xh, wh, owh);

    // 1) RPE bias projection
    rpe_bias_kernel<<<512, 256>>>(rel_pos, rpe_w);

    // 2) QKV projection -> Q,K (half) + V transposed (half)
    {
        dim3 grid(3 * Dv / 128, BT / 128);
        f16_gemm<1><<<grid, 256, GSM_B>>>(xh, wh, qkv_b, nullptr,
                                          qh, kh, vT, BT, 3 * Dv, Dv);
    }

    // 3) flash attention with RPE (ldmatrix + register-resident P)
    {
        dim3 grid(Tv / QT, Hv, Bv);
        flash_rpe_f16<<<grid, 256, FSM_B>>>();
    }

    // 4) output projection -> fp32 out
    {
        dim3 grid(Dv / 128, BT / 128);
        f16_gemm<0><<<grid, 256, GSM_B>>>(attnh, owh, out_b, out,
                                          nullptr, nullptr, nullptr,
                                          BT, Dv, Dv);
    }
}

// round 11
// speedup vs baseline: 7.5494x; 1.0318x over previous
#include <cuda_runtime.h>
#include <cuda_fp16.h>
#include <math.h>
#include <stdint.h>

// Problem constants
#define Bv      2
#define Tv      2048
#define Dv      1024
#define Hv      16
#define HDv     64
#define MAXLEN  2048
#define NBIAS   (2 * MAXLEN - 1)   // 4095
#define BT      (Bv * Tv)          // 4096

// ---------------------------------------------------------------------------
// Scratch (device globals)
// ---------------------------------------------------------------------------
__device__ float  g_bias[4608];             // projected RPE bias (zero-padded)
__device__ __half g_xh[BT * Dv];            // x      (half)
__device__ __half g_wh[3 * Dv * Dv];        // qkv_w  (half)
__device__ __half g_owh[Dv * Dv];           // out_w  (half)
__device__ __half g_qh[BT * Dv];            // Q      [b*T+t][h*64+d]
__device__ __half g_kh[BT * Dv];            // K      [b*T+t][h*64+d]
__device__ __half g_vT[Bv * Hv * HDv * Tv]; // V^T  [(b*16+h)*64+d][token]
__device__ __half g_attnh[BT * Dv];         // attention output (half)

// ---------------------------------------------------------------------------
// PTX helpers (sm_103-base safe: cp.async + mma.sync + ldmatrix)
// ---------------------------------------------------------------------------
__device__ __forceinline__ uint32_t smem_u32(const void* p) {
    uint32_t a;
    asm("{ .reg .u64 t; cvta.to.shared.u64 t, %1; cvt.u32.u64 %0, t; }"
        : "=r"(a) : "l"(p));
    return a;
}
__device__ __forceinline__ void cp_async16(uint32_t saddr, const void* gptr) {
    asm volatile("cp.async.cg.shared.global [%0], [%1], 16;"
                 :: "r"(saddr), "l"(gptr) : "memory");
}
#define CP_COMMIT() asm volatile("cp.async.commit_group;" ::: "memory")
#define CP_WAIT(n)  asm volatile("cp.async.wait_group %0;" :: "n"(n) : "memory")

__device__ __forceinline__ void ldsm_x4(uint32_t r[4], uint32_t addr) {
    asm volatile("ldmatrix.sync.aligned.m8n8.x4.shared.b16 {%0,%1,%2,%3}, [%4];"
                 : "=r"(r[0]), "=r"(r[1]), "=r"(r[2]), "=r"(r[3])
                 : "r"(addr));
}
__device__ __forceinline__ void mma_f16(float c[4], const uint32_t a[4],
                                        const uint32_t b[2]) {
    asm volatile(
        "mma.sync.aligned.m16n8k16.row.col.f32.f16.f16.f32 "
        "{%0,%1,%2,%3}, {%4,%5,%6,%7}, {%8,%9}, {%0,%1,%2,%3};"
        : "+f"(c[0]), "+f"(c[1]), "+f"(c[2]), "+f"(c[3])
        : "r"(a[0]), "r"(a[1]), "r"(a[2]), "r"(a[3]),
          "r"(b[0]), "r"(b[1]));
}
__device__ __forceinline__ uint32_t pack_h2(float lo, float hi) {
    __half2 h = __floats2half2_rn(lo, hi);
    return *(uint32_t*)&h;
}

// ---------------------------------------------------------------------------
// Kernel 0: fused prep — fp32->fp16 converts (x, qkv_w, out_w) + RPE bias
// cvt blocks [0,8192): units of 4 elems; bias blocks [8192,8704): 8 j/block
// ---------------------------------------------------------------------------
__global__ void prep_kernel(const float* __restrict__ x,
                            const float* __restrict__ w,
                            const float* __restrict__ ow,
                            const float* __restrict__ rel_pos,
                            const float* __restrict__ rpe_w,
                            __half* __restrict__ xh,
                            __half* __restrict__ wh,
                            __half* __restrict__ owh) {
    if (blockIdx.x < 8192) {
        int u = blockIdx.x * blockDim.x + threadIdx.x;
        const float* src;
        __half* dst;
        int idx;
        if (u < 1048576)       { src = x;  dst = xh;  idx = u; }
        else if (u < 1835008)  { src = w;  dst = wh;  idx = u - 1048576; }
        else                   { src = ow; dst = owh; idx = u - 1835008; }
        int i = idx * 4;
        float4 v = *(const float4*)(src + i);
        uint2 o;
        o.x = pack_h2(v.x, v.y);
        o.y = pack_h2(v.z, v.w);
        *(uint2*)&dst[i] = o;
    } else {
        int wid = threadIdx.x >> 5, lane = threadIdx.x & 31;
        int j = (blockIdx.x - 8192) * 8 + wid;
        if (j >= NBIAS) return;
        float v = rel_pos[j * HDv + lane] * rpe_w[lane]
                + rel_pos[j * HDv + 32 + lane] * rpe_w[32 + lane];
        #pragma unroll
        for (int o = 16; o > 0; o >>= 1) v += __shfl_xor_sync(0xffffffffu, v, o);
        if (lane == 0) g_bias[j] = v;
    }
}

// ---------------------------------------------------------------------------
// fp16 mma.sync GEMM with ldmatrix fragment feed (unchanged from R10).
// ---------------------------------------------------------------------------
#define BKH    64
#define PAG    36
#define TILEU  (128 * PAG)
#define STGU   (2 * TILEU)
#define GSM_B  (2 * STGU * 4)          // 73728 bytes

template<int MODE>
__global__ void __launch_bounds__(256, 2)
f16_gemm(const __half* __restrict__ A, const __half* __restrict__ W,
         const float* __restrict__ bias, float* __restrict__ Cf,
         __half* __restrict__ qh, __half* __restrict__ kh,
         __half* __restrict__ vT, int M, int N, int K) {
    extern __shared__ uint32_t smu[];
    const uint32_t sbase = smem_u32(smu);
    const int tid  = threadIdx.x;
    const int wid  = tid >> 5;
    const int lane = tid & 31;
    const int q    = lane >> 2;
    const int t    = lane & 3;
    const int warp_m = wid >> 2;
    const int warp_n = wid & 3;
    const int bm = blockIdx.y * 128;
    const int bn = blockIdx.x * 128;
    const int nchunk = K / BKH;

    const int lr   = lane & 15;
    const int lc   = (lane >> 4) * 4;
    const int brow = (lane & 7) | ((lane >> 4) << 3);
    const int bsub = ((lane >> 3) & 1) * 4;

    float acc[4][4][4];
    #pragma unroll
    for (int mi = 0; mi < 4; ++mi)
        #pragma unroll
        for (int ni = 0; ni < 4; ++ni)
            #pragma unroll
            for (int e = 0; e < 4; ++e) acc[mi][ni][e] = 0.f;

    auto load_chunk = [&](int c, int s) {
        const uint32_t ab = sbase + s * (STGU * 4);
        const uint32_t bb = ab + TILEU * 4;
        #pragma unroll
        for (int i = 0; i < 4; ++i) {
            int idx = tid + 256 * i;
            int row = idx >> 3;
            int cc  = idx & 7;
            uint32_t doff = (uint32_t)(row * PAG + cc * 4) * 4;
            cp_async16(ab + doff, A + (size_t)(bm + row) * K + c * BKH + cc * 8);
            cp_async16(bb + doff, W + (size_t)(bn + row) * K + c * BKH + cc * 8);
        }
    };

    load_chunk(0, 0); CP_COMMIT();
    load_chunk(1, 1); CP_COMMIT();

    uint32_t a_base[4], b_base[2];
    #pragma unroll
    for (int mi = 0; mi < 4; ++mi)
        a_base[mi] = sbase + (uint32_t)((warp_m * 64 + mi * 16 + lr) * PAG + lc) * 4;
    #pragma unroll
    for (int p = 0; p < 2; ++p)
        b_base[p] = sbase + (uint32_t)(TILEU + (warp_n * 32 + p * 16 + brow) * PAG + bsub) * 4;

    for (int c = 0; c < nchunk; ++c) {
        const int s = c & 1;
        if (c + 1 < nchunk) { CP_WAIT(1); } else { CP_WAIT(0); }
        __syncthreads();
        const uint32_t soff = (uint32_t)(s * STGU * 4);

        #pragma unroll
        for (int ks = 0; ks < 4; ++ks) {
            const uint32_t ko = soff + ks * 32;
            uint32_t af[4][4], bq[2][4];
            #pragma unroll
            for (int mi = 0; mi < 4; ++mi) ldsm_x4(af[mi], a_base[mi] + ko);
            #pragma unroll
            for (int p = 0; p < 2; ++p)   ldsm_x4(bq[p], b_base[p] + ko);
            #pragma unroll
            for (int mi = 0; mi < 4; ++mi)
                #pragma unroll
                for (int ni = 0; ni < 4; ++ni)
                    mma_f16(acc[mi][ni], af[mi], &bq[ni >> 1][(ni & 1) * 2]);
        }

        __syncthreads();
        if (c + 2 < nchunk) { load_chunk(c + 2, s); CP_COMMIT(); }
    }

    #pragma unroll
    for (int mi = 0; mi < 4; ++mi) {
        const int row0 = bm + warp_m * 64 + mi * 16 + q;
        #pragma unroll
        for (int ni = 0; ni < 4; ++ni) {
            const int col = bn + warp_n * 32 + ni * 8 + 2 * t;
            const float b0 = bias[col], b1 = bias[col + 1];
            float o00 = acc[mi][ni][0] + b0, o01 = acc[mi][ni][1] + b1;
            float o10 = acc[mi][ni][2] + b0, o11 = acc[mi][ni][3] + b1;
            if (MODE == 0) {
                *(float2*)&Cf[(size_t)row0 * N + col] = make_float2(o00, o01);
                *(float2*)&Cf[(size_t)(row0 + 8) * N + col] = make_float2(o10, o11);
            } else {
                if (bn < 2048) {
                    __half* dst = (bn < 1024) ? qh : kh;
                    int coln = (bn < 1024) ? col : col - 1024;
                    *(uint32_t*)&dst[(size_t)row0 * 1024 + coln] = pack_h2(o00, o01);
                    *(uint32_t*)&dst[(size_t)(row0 + 8) * 1024 + coln] = pack_h2(o10, o11);
                } else {
                    int hd = col - 2048;
                    int h = hd >> 6, d = hd & 63;
                    int bb = row0 >> 11, token = row0 & 2047;
                    __half* base = vT + ((size_t)((bb * 16 + h) * 64 + d)) * 2048 + token;
                    base[0]        = __float2half_rn(o00);
                    base[2048]     = __float2half_rn(o01);
                    base[8]        = __float2half_rn(o10);
                    base[2048 + 8] = __float2half_rn(o11);
                }
            }
        }
    }
}

// ---------------------------------------------------------------------------
// Kernel 3: flash attention with RPE, fp16 mma + ldmatrix.
// 4 warps x 32 q-rows (two 16-row m-tiles/warp) -> K/V frags reused 2x,
// halving smem crossbar traffic. 128 threads, 3 CTAs/SM.
// ---------------------------------------------------------------------------
#define QT    128
#define KT    64
#define QPA   36
#define VPA   36
#define OFF_Q   0
#define OFF_K   (OFF_Q + QT * QPA)
#define OFF_V   (OFF_K + 2 * KT * QPA)
#define OFF_BW  (OFF_V + 2 * HDv * VPA)
#define FSMU    (OFF_BW + 2 * 192)
#define FSM_B   (FSMU * 4)               // 56832 bytes

__global__ void __launch_bounds__(128, 3)
flash_rpe_f16() {
    extern __shared__ uint32_t smu[];
    const uint32_t sb = smem_u32(smu);
    float* smf = (float*)smu;
    const int b = blockIdx.z, h = blockIdx.y;
    const int qbase = blockIdx.x * QT;
    const int tid = threadIdx.x, wid = tid >> 5, lane = tid & 31;
    const int q = lane >> 2, t = lane & 3;
    const int mb = wid * 32;               // warp owns 32 q-rows
    const float scale = 0.125f;

    const int lr   = lane & 15;
    const int lc   = (lane >> 4) * 4;
    const int brow = (lane & 7) | ((lane >> 4) << 3);
    const int bsub = ((lane >> 3) & 1) * 4;

    // ---- Q tile via cp.async (group 0 with kv0) ----
    #pragma unroll
    for (int i = 0; i < 8; ++i) {
        int idx = tid + 128 * i;           // 0..1023
        int row = idx >> 3;                // 0..127
        int c8  = idx & 7;
        cp_async16(sb + (uint32_t)(OFF_Q + row * QPA + c8 * 4) * 4,
                   g_qh + (size_t)(b * Tv + qbase + row) * 1024 + h * 64 + c8 * 8);
    }

    auto load_kv = [&](int kt, int s) {
        const int kbase = kt * KT;
        const uint32_t kb = sb + (uint32_t)(OFF_K + s * KT * QPA) * 4;
        const uint32_t vb = sb + (uint32_t)(OFF_V + s * HDv * VPA) * 4;
        #pragma unroll
        for (int i = 0; i < 4; ++i) {
            int idx = tid + 128 * i;       // 0..511
            int row = idx >> 3;            // 0..63
            int c8  = idx & 7;
            cp_async16(kb + (uint32_t)(row * QPA + c8 * 4) * 4,
                       g_kh + (size_t)(b * Tv + kbase + row) * 1024 + h * 64 + c8 * 8);
            cp_async16(vb + (uint32_t)(row * VPA + c8 * 4) * 4,
                       g_vT + (size_t)((b * 16 + h) * 64 + row) * 2048 + kbase + c8 * 8);
        }
        if (tid < 48) {
            int base = kbase - qbase + 1920;
            cp_async16(sb + (uint32_t)(OFF_BW + s * 192 + tid * 4) * 4,
                       &g_bias[base + tid * 4]);
        }
    };

    load_kv(0, 0); CP_COMMIT();
    load_kv(1, 1); CP_COMMIT();

    // invariant ldmatrix bases
    uint32_t q_base[2];
    #pragma unroll
    for (int mt = 0; mt < 2; ++mt)
        q_base[mt] = sb + (uint32_t)(OFF_Q + (mb + mt * 16 + lr) * QPA + lc) * 4;
    uint32_t k_base[4], v_base[4];
    #pragma unroll
    for (int p = 0; p < 4; ++p) {
        k_base[p] = sb + (uint32_t)(OFF_K + (p * 16 + brow) * QPA + bsub) * 4;
        v_base[p] = sb + (uint32_t)(OFF_V + (p * 16 + brow) * VPA + bsub) * 4;
    }

    // online softmax state: [2*mt + (0: row q, 1: row q+8)]
    float m[4], l[4];
    #pragma unroll
    for (int i = 0; i < 4; ++i) { m[i] = -INFINITY; l[i] = 0.f; }
    float ao[2][8][4];
    #pragma unroll
    for (int mt = 0; mt < 2; ++mt)
        #pragma unroll
        for (int ni = 0; ni < 8; ++ni)
            #pragma unroll
            for (int e = 0; e < 4; ++e) ao[mt][ni][e] = 0.f;

    const int NIT = Tv / KT;   // 32
    for (int kt = 0; kt < NIT; ++kt) {
        const int s = kt & 1;
        if (kt < NIT - 1) { CP_WAIT(1); } else { CP_WAIT(0); }
        __syncthreads();

        const uint32_t ksoff = (uint32_t)(s * KT * QPA * 4);
        const uint32_t vsoff = (uint32_t)(s * HDv * VPA * 4);
        const float* bw = smf + OFF_BW + s * 192;

        // ---- S = Q K^T : 2 m-tiles share each K fragment ----
        float as_[2][8][4];
        #pragma unroll
        for (int mt = 0; mt < 2; ++mt)
            #pragma unroll
            for (int ni = 0; ni < 8; ++ni)
                #pragma unroll
                for (int e = 0; e < 4; ++e) as_[mt][ni][e] = 0.f;

        #pragma unroll
        for (int ks = 0; ks < 4; ++ks) {
            const uint32_t ko = ks * 32;
            uint32_t af0[4], af1[4];
            ldsm_x4(af0, q_base[0] + ko);
            ldsm_x4(af1, q_base[1] + ko);
            #pragma unroll
            for (int p = 0; p < 4; ++p) {
                uint32_t kq[4];
                ldsm_x4(kq, k_base[p] + ksoff + ko);
                mma_f16(as_[0][2 * p],     af0, &kq[0]);
                mma_f16(as_[0][2 * p + 1], af0, &kq[2]);
                mma_f16(as_[1][2 * p],     af1, &kq[0]);
                mma_f16(as_[1][2 * p + 1], af1, &kq[2]);
            }
        }

        // ---- softmax per m-tile ----
        uint32_t pf[2][8][2];
        #pragma unroll
        for (int mt = 0; mt < 2; ++mt) {
            const int rowb = mb + mt * 16;
            float mx0 = -INFINITY, mx1 = -INFINITY;
            #pragma unroll
            for (int ni = 0; ni < 8; ++ni) {
                const int i0 = ni * 8 + 2 * t - rowb - q + 127;
                as_[mt][ni][0] = fmaf(as_[mt][ni][0], scale, bw[i0]);
                as_[mt][ni][1] = fmaf(as_[mt][ni][1], scale, bw[i0 + 1]);
                as_[mt][ni][2] = fmaf(as_[mt][ni][2], scale, bw[i0 - 8]);
                as_[mt][ni][3] = fmaf(as_[mt][ni][3], scale, bw[i0 - 7]);
                mx0 = fmaxf(mx0, fmaxf(as_[mt][ni][0], as_[mt][ni][1]));
                mx1 = fmaxf(mx1, fmaxf(as_[mt][ni][2], as_[mt][ni][3]));
            }
            #pragma unroll
            for (int off = 1; off <= 2; off <<= 1) {
                mx0 = fmaxf(mx0, __shfl_xor_sync(0xffffffffu, mx0, off));
                mx1 = fmaxf(mx1, __shfl_xor_sync(0xffffffffu, mx1, off));
            }
            const float mn0 = fmaxf(m[2 * mt], mx0);
            const float mn1 = fmaxf(m[2 * mt + 1], mx1);
            const float c0 = __expf(m[2 * mt] - mn0);
            const float c1 = __expf(m[2 * mt + 1] - mn1);
            m[2 * mt] = mn0; m[2 * mt + 1] = mn1;

            float rs0 = 0.f, rs1 = 0.f;
            #pragma unroll
            for (int ni = 0; ni < 8; ++ni) {
                float p0 = __expf(as_[mt][ni][0] - mn0);
                float p1 = __expf(as_[mt][ni][1] - mn0);
                float p2 = __expf(as_[mt][ni][2] - mn1);
                float p3 = __expf(as_[mt][ni][3] - mn1);
                rs0 += p0 + p1; rs1 += p2 + p3;
                pf[mt][ni][0] = pack_h2(p0, p1);
                pf[mt][ni][1] = pack_h2(p2, p3);
            }
            #pragma unroll
            for (int off = 1; off <= 2; off <<= 1) {
                rs0 += __shfl_xor_sync(0xffffffffu, rs0, off);
                rs1 += __shfl_xor_sync(0xffffffffu, rs1, off);
            }
            l[2 * mt]     = l[2 * mt] * c0 + rs0;
            l[2 * mt + 1] = l[2 * mt + 1] * c1 + rs1;
            #pragma unroll
            for (int ni = 0; ni < 8; ++ni) {
                ao[mt][ni][0] *= c0; ao[mt][ni][1] *= c0;
                ao[mt][ni][2] *= c1; ao[mt][ni][3] *= c1;
            }
        }

        // ---- O += P @ V : V fragments shared across both m-tiles ----
        #pragma unroll
        for (int ks = 0; ks < 4; ++ks) {
            const uint32_t ko = ks * 32;
            uint32_t a0[4], a1[4];
            a0[0] = pf[0][2 * ks][0];     a0[1] = pf[0][2 * ks][1];
            a0[2] = pf[0][2 * ks + 1][0]; a0[3] = pf[0][2 * ks + 1][1];
            a1[0] = pf[1][2 * ks][0];     a1[1] = pf[1][2 * ks][1];
            a1[2] = pf[1][2 * ks + 1][0]; a1[3] = pf[1][2 * ks + 1][1];
            #pragma unroll
            for (int p = 0; p < 4; ++p) {
                uint32_t vq[4];
                ldsm_x4(vq, v_base[p] + vsoff + ko);
                mma_f16(ao[0][2 * p],     a0, &vq[0]);
                mma_f16(ao[0][2 * p + 1], a0, &vq[2]);
                mma_f16(ao[1][2 * p],     a1, &vq[0]);
                mma_f16(ao[1][2 * p + 1], a1, &vq[2]);
            }
        }

        __syncthreads();
        if (kt + 2 < NIT) { load_kv(kt + 2, s); CP_COMMIT(); }
    }

    // ---- normalize, write half attn ----
    #pragma unroll
    for (int mt = 0; mt < 2; ++mt) {
        const float inv0 = 1.f / l[2 * mt];
        const float inv1 = 1.f / l[2 * mt + 1];
        const int r0 = qbase + mb + mt * 16 + q;
        #pragma unroll
        for (int ni = 0; ni < 8; ++ni) {
            const int col = h * HDv + ni * 8 + 2 * t;
            *(uint32_t*)&g_attnh[(size_t)(b * Tv + r0) * Dv + col]
                = pack_h2(ao[mt][ni][0] * inv0, ao[mt][ni][1] * inv0);
            *(uint32_t*)&g_attnh[(size_t)(b * Tv + r0 + 8) * Dv + col]
                = pack_h2(ao[mt][ni][2] * inv1, ao[mt][ni][3] * inv1);
        }
    }
}

// ---------------------------------------------------------------------------
// Launcher
// ---------------------------------------------------------------------------
extern "C" void kernel_launch(void* const* d_in, const int* in_sizes, int n_in,
                              void* d_out, int out_size) {
    const float* x       = (const float*)d_in[0];
    const float* qkv_w   = (const float*)d_in[1];
    const float* qkv_b   = (const float*)d_in[2];
    const float* out_w   = (const float*)d_in[3];
    const float* out_b   = (const float*)d_in[4];
    const float* rel_pos = (const float*)d_in[5];
    const float* rpe_w   = (const float*)d_in[6];
    float* out = (float*)d_out;

    __half *xh, *wh, *owh, *qh, *kh, *vT, *attnh;
    cudaGetSymbolAddress((void**)&xh,    g_xh);
    cudaGetSymbolAddress((void**)&wh,    g_wh);
    cudaGetSymbolAddress((void**)&owh,   g_owh);
    cudaGetSymbolAddress((void**)&qh,    g_qh);
    cudaGetSymbolAddress((void**)&kh,    g_kh);
    cudaGetSymbolAddress((void**)&vT,    g_vT);
    cudaGetSymbolAddress((void**)&attnh, g_attnh);

    cudaFuncSetAttribute(f16_gemm<0>,
                         cudaFuncAttributeMaxDynamicSharedMemorySize, GSM_B);
    cudaFuncSetAttribute(f16_gemm<1>,
                         cudaFuncAttributeMaxDynamicSharedMemorySize, GSM_B);
    cudaFuncSetAttribute(flash_rpe_f16,
                         cudaFuncAttributeMaxDynamicSharedMemorySize, FSM_B);

    // 0) fused converts + RPE bias projection
    prep_kernel<<<8704, 256>>>(x, qkv_w, out_w, rel_pos, rpe_w, xh, wh, owh);

    // 1) QKV projection -> Q,K (half) + V transposed (half)
    {
        dim3 grid(3 * Dv / 128, BT / 128);
        f16_gemm<1><<<grid, 256, GSM_B>>>(xh, wh, qkv_b, nullptr,
                                          qh, kh, vT, BT, 3 * Dv, Dv);
    }

    // 2) flash attention with RPE (2 m-tiles/warp, 3 CTAs/SM)
    {
        dim3 grid(Tv / QT, Hv, Bv);
        flash_rpe_f16<<<grid, 128, FSM_B>>>();
    }

    // 3) output projection -> fp32 out
    {
        dim3 grid(Dv / 128, BT / 128);
        f16_gemm<0><<<grid, 256, GSM_B>>>(attnh, owh, out_b, out,
                                          nullptr, nullptr, nullptr,
                                          BT, Dv, Dv);
    }
}